// round 10
// baseline (speedup 1.0000x reference)
#include <cuda_runtime.h>
#include <cuda_bf16.h>
#include <math.h>
#include <cstdint>

// Problem constants (fixed by the dataset)
#define B    4
#define N    16384
#define C    256
#define C3   768
#define T    64        // categories
#define HDS  8
#define D    32        // head dim
#define GS   128       // group size
#define NG   128       // groups per batch
#define CHUNK 128
#define NCH   128      // N / CHUNK

// ---------------- scratch (static device allocations only) ----------------
__device__ int   g_tkid[B * N];
__device__ int   g_counts[B * T * NCH];     // [b][key][chunk], scanned in place
__device__ int   g_sortidx[B * N];          // sorted position -> original token
// attention output in ORIGINAL token order, pre-split bf16 hi/lo
__device__ __nv_bfloat16 g_yh[(size_t)B * N * C];
__device__ __nv_bfloat16 g_yl[(size_t)B * N * C];
// pre-split projection weight
__device__ __nv_bfloat16 g_wh[C * C];
__device__ __nv_bfloat16 g_wl[C * C];

// bf16 hi/lo split of a pair of floats, packed as bf16x2 words
__device__ __forceinline__ void split2(float a, float b, uint32_t& hi, uint32_t& lo) {
    __nv_bfloat162 h = __floats2bfloat162_rn(a, b);
    float ra = a - __bfloat162float(h.x);
    float rb = b - __bfloat162float(h.y);
    __nv_bfloat162 l = __floats2bfloat162_rn(ra, rb);
    hi = *(uint32_t*)&h;
    lo = *(uint32_t*)&l;
}

// warp-level bf16 MMA, fp32 accumulate (sm_80+, no arch-feature gate)
__device__ __forceinline__ void mma16816(float* c, const uint32_t* a, const uint32_t* b) {
    asm volatile(
        "mma.sync.aligned.m16n8k16.row.col.f32.bf16.bf16.f32 "
        "{%0,%1,%2,%3}, {%4,%5,%6,%7}, {%8,%9}, {%0,%1,%2,%3};"
        : "+f"(c[0]), "+f"(c[1]), "+f"(c[2]), "+f"(c[3])
        : "r"(a[0]), "r"(a[1]), "r"(a[2]), "r"(a[3]), "r"(b[0]), "r"(b[1]));
}

__device__ __forceinline__ uint32_t smem_u32(const void* p) {
    uint32_t a;
    asm("{ .reg .u64 t; cvta.to.shared.u64 t, %1; cvt.u32.u64 %0, t; }"
        : "=r"(a) : "l"(p));
    return a;
}
__device__ __forceinline__ void ldsm4(uint32_t* r, uint32_t addr) {
    asm volatile("ldmatrix.sync.aligned.m8n8.x4.shared.b16 {%0,%1,%2,%3}, [%4];"
                 : "=r"(r[0]), "=r"(r[1]), "=r"(r[2]), "=r"(r[3]) : "r"(addr));
}

// ---------------- K0: pre-split W into bf16 hi/lo (runs once per launch) -----
__global__ void k_wsplit(const float* __restrict__ W) {
    int i = blockIdx.x * 256 + threadIdx.x;   // 16384 float4s
    float4 v = ((const float4*)W)[i];
    uint32_t h0, l0, h1, l1;
    split2(v.x, v.y, h0, l0);
    split2(v.z, v.w, h1, l1);
    *(uint2*)(g_wh + i * 4) = make_uint2(h0, h1);
    *(uint2*)(g_wl + i * 4) = make_uint2(l0, l1);
}

// ---------------- K1: per-token argmax + per-chunk histogram ----------------
__global__ void k_argmax_count(const float* __restrict__ sim) {
    int b = blockIdx.y, ch = blockIdx.x, tid = threadIdx.x;
    __shared__ float ss[CHUNK * T];   // 32 KB
    __shared__ int   hist[T];

    const float4* src = (const float4*)(sim + ((size_t)(b * N + ch * CHUNK)) * T);
    float4* dst = (float4*)ss;
#pragma unroll
    for (int i = tid; i < CHUNK * T / 4; i += CHUNK) dst[i] = src[i];
    if (tid < T) hist[tid] = 0;
    __syncthreads();

    const float* row = ss + tid * T;
    float best = row[0];
    int   bi   = 0;
#pragma unroll
    for (int j = 1; j < T; j++) {
        float v = row[j];
        if (v > best) { best = v; bi = j; }   // first-max == jnp.argmax tie rule
    }
    g_tkid[b * N + ch * CHUNK + tid] = bi;
    atomicAdd(&hist[bi], 1);
    __syncthreads();
    if (tid < T) g_counts[(b * T + tid) * NCH + ch] = hist[tid];
}

// ---------------- K2: per-batch exclusive scan of counts (8192 ints) ----------------
__global__ void k_scan() {
    const int PER = (T * NCH) / 1024;   // 8
    int b = blockIdx.x, tid = threadIdx.x;
    __shared__ int t1[1024], t2[1024];
    int* cnt = g_counts + b * T * NCH;

    int v[PER];
    int s = 0;
#pragma unroll
    for (int i = 0; i < PER; i++) { v[i] = cnt[tid * PER + i]; s += v[i]; }
    t1[tid] = s;
    __syncthreads();

    int* a  = t1;
    int* bb = t2;
    for (int off = 1; off < 1024; off <<= 1) {
        int x = a[tid];
        if (tid >= off) x += a[tid - off];
        bb[tid] = x;
        __syncthreads();
        int* tmp = a; a = bb; bb = tmp;
    }
    int pre = (tid == 0) ? 0 : a[tid - 1];
#pragma unroll
    for (int i = 0; i < PER; i++) { cnt[tid * PER + i] = pre; pre += v[i]; }
}

// ---------------- K3: stable scatter (match_any rank, no serial loop) --------
__global__ void k_scatter() {
    int b = blockIdx.y, ch = blockIdx.x, tid = threadIdx.x;
    __shared__ int wcnt[4][T];
    int w = tid >> 5, lane = tid & 31;
    for (int i = tid; i < 4 * T; i += CHUNK) ((int*)wcnt)[i] = 0;
    __syncthreads();

    int token = ch * CHUNK + tid;
    int key   = g_tkid[b * N + token];
    unsigned mask  = __match_any_sync(0xffffffffu, key);
    int lrank  = __popc(mask & ((1u << lane) - 1));
    int leader = __ffs(mask) - 1;
    if (lane == leader) wcnt[w][key] = __popc(mask);
    __syncthreads();

    int rank = lrank;
#pragma unroll
    for (int ww = 0; ww < 4; ww++)
        if (ww < w) rank += wcnt[ww][key];
    int pos = g_counts[(b * T + key) * NCH + ch] + rank;
    g_sortidx[b * N + pos] = token;
}

// ---------------- K4: grouped attention via warp MMA (bf16 3-term split) -----
// One CTA (256 thr / 8 warps) per (head, group, batch); warp owns 16 q-rows.
// Q,K smem rows padded to 40 bf16 (80 B): ldmatrix conflict-free.
// V transposed Vt[dim][key], rows 136 bf16 (68 words, 68%32=4) -> conflict-free.
#define ATP 40
#define VTP 136
#define SQH 0
#define SQL (SQH + GS * ATP * 2)          // 10240 each
#define SKH (SQL + GS * ATP * 2)
#define SKL (SKH + GS * ATP * 2)
#define SVH (SKL + GS * ATP * 2)          // Vt: 32*272 = 8704 each
#define SVL (SVH + D * VTP * 2)
#define STOK (SVL + D * VTP * 2)
#define SM_ATTN (STOK + GS * 4)           // 58,880 B

__global__ void __launch_bounds__(256, 2)
k_attn_mma(const float* __restrict__ qkv, const float* __restrict__ logit_scale) {
    extern __shared__ char sm[];
    uint32_t sb = smem_u32(sm);
    int head = blockIdx.x, g = blockIdx.y, b = blockIdx.z;
    int tid = threadIdx.x;
    int* toks = (int*)(sm + STOK);

    int r = tid >> 1, h = tid & 1;           // 2 threads per token row
    int token = g_sortidx[b * N + g * GS + r];
    if (h == 0) toks[r] = token;

    float scale = __expf(fminf(logit_scale[0], 4.6051701859880914f));  // log(100)

    // ---- gather: split q (pre-scaled), k into smem; v transposed ----
    const float4* base =
        (const float4*)(qkv + ((size_t)(b * N) + token) * C3 + head * D);
#pragma unroll
    for (int p = h * 4; p < h * 4 + 4; p += 2) {   // q: 2 float4 pairs
        float4 v0 = base[p], v1 = base[p + 1];
        v0.x *= scale; v0.y *= scale; v0.z *= scale; v0.w *= scale;
        v1.x *= scale; v1.y *= scale; v1.z *= scale; v1.w *= scale;
        uint32_t h0, l0, h1, l1, h2, l2, h3, l3;
        split2(v0.x, v0.y, h0, l0); split2(v0.z, v0.w, h1, l1);
        split2(v1.x, v1.y, h2, l2); split2(v1.z, v1.w, h3, l3);
        *(uint2*)(sm + SQH + r * (ATP * 2) + p * 8)     = make_uint2(h0, h1);
        *(uint2*)(sm + SQH + r * (ATP * 2) + p * 8 + 8) = make_uint2(h2, h3);
        *(uint2*)(sm + SQL + r * (ATP * 2) + p * 8)     = make_uint2(l0, l1);
        *(uint2*)(sm + SQL + r * (ATP * 2) + p * 8 + 8) = make_uint2(l2, l3);
    }
#pragma unroll
    for (int p = h * 4; p < h * 4 + 4; p += 2) {   // k (+256 floats = +64 float4)
        float4 v0 = base[64 + p], v1 = base[64 + p + 1];
        uint32_t h0, l0, h1, l1, h2, l2, h3, l3;
        split2(v0.x, v0.y, h0, l0); split2(v0.z, v0.w, h1, l1);
        split2(v1.x, v1.y, h2, l2); split2(v1.z, v1.w, h3, l3);
        *(uint2*)(sm + SKH + r * (ATP * 2) + p * 8)     = make_uint2(h0, h1);
        *(uint2*)(sm + SKH + r * (ATP * 2) + p * 8 + 8) = make_uint2(h2, h3);
        *(uint2*)(sm + SKL + r * (ATP * 2) + p * 8)     = make_uint2(l0, l1);
        *(uint2*)(sm + SKL + r * (ATP * 2) + p * 8 + 8) = make_uint2(l2, l3);
    }
    {
        __nv_bfloat16* vh = (__nv_bfloat16*)(sm + SVH);
        __nv_bfloat16* vl = (__nv_bfloat16*)(sm + SVL);
#pragma unroll
        for (int p = h * 4; p < h * 4 + 4; p++) {  // v (+512 floats = +128 float4)
            float4 v = base[128 + p];
            uint32_t h0, l0, h1, l1;
            split2(v.x, v.y, h0, l0);
            split2(v.z, v.w, h1, l1);
            __nv_bfloat162 H0 = *(__nv_bfloat162*)&h0, L0 = *(__nv_bfloat162*)&l0;
            __nv_bfloat162 H1 = *(__nv_bfloat162*)&h1, L1 = *(__nv_bfloat162*)&l1;
            int d0 = p * 4;
            vh[(d0 + 0) * VTP + r] = H0.x;  vl[(d0 + 0) * VTP + r] = L0.x;
            vh[(d0 + 1) * VTP + r] = H0.y;  vl[(d0 + 1) * VTP + r] = L0.y;
            vh[(d0 + 2) * VTP + r] = H1.x;  vl[(d0 + 2) * VTP + r] = L1.x;
            vh[(d0 + 3) * VTP + r] = H1.y;  vl[(d0 + 3) * VTP + r] = L1.y;
        }
    }
    __syncthreads();

    int w = tid >> 5, lane = tid & 31;
    int gq = lane >> 2, t = lane & 3;
    int quad = lane >> 3, rrow = lane & 7;   // ldmatrix lane decomposition

    // ---- Q fragments via ldmatrix.x4 (A-operand, 16 rows x k16 per ki) ----
    uint32_t qh[2][4], ql[2][4];
    {
        int qrow = w * 16 + (quad & 1) * 8 + rrow;
#pragma unroll
        for (int ki = 0; ki < 2; ki++) {
            uint32_t off = qrow * 80 + ki * 32 + (quad >> 1) * 16;
            ldsm4(qh[ki], sb + SQH + off);
            ldsm4(ql[ki], sb + SQL + off);
        }
    }

    // ---- S = (scale*Q) K^T, 16x128 per warp in registers ----
    float S[16][4];
#pragma unroll
    for (int ni = 0; ni < 16; ni++)
#pragma unroll
        for (int rr = 0; rr < 4; rr++) S[ni][rr] = 0.f;

#pragma unroll
    for (int np = 0; np < 8; np++) {         // pairs of 8-key B tiles
        int krow = np * 16 + (quad >> 1) * 8 + rrow;
#pragma unroll
        for (int ki = 0; ki < 2; ki++) {
            uint32_t off = krow * 80 + ki * 32 + (quad & 1) * 16;
            uint32_t bh[4], bl[4];
            ldsm4(bh, sb + SKH + off);       // {b0,b1}=ni_even, {b2,b3}=ni_odd
            ldsm4(bl, sb + SKL + off);
            mma16816(S[2 * np],     qh[ki], bh);
            mma16816(S[2 * np],     qh[ki], bl);
            mma16816(S[2 * np],     ql[ki], bh);
            mma16816(S[2 * np + 1], qh[ki], bh + 2);
            mma16816(S[2 * np + 1], qh[ki], bl + 2);
            mma16816(S[2 * np + 1], ql[ki], bh + 2);
        }
    }

    // ---- softmax (two-pass, quad-shuffle row reductions) ----
    float mx0 = -INFINITY, mx1 = -INFINITY;
#pragma unroll
    for (int ni = 0; ni < 16; ni++) {
        mx0 = fmaxf(mx0, fmaxf(S[ni][0], S[ni][1]));
        mx1 = fmaxf(mx1, fmaxf(S[ni][2], S[ni][3]));
    }
#pragma unroll
    for (int x = 1; x <= 2; x <<= 1) {
        mx0 = fmaxf(mx0, __shfl_xor_sync(0xffffffffu, mx0, x));
        mx1 = fmaxf(mx1, __shfl_xor_sync(0xffffffffu, mx1, x));
    }

    float sm0 = 0.f, sm1 = 0.f;
#pragma unroll
    for (int ni = 0; ni < 16; ni++) {
        S[ni][0] = __expf(S[ni][0] - mx0);
        S[ni][1] = __expf(S[ni][1] - mx0);
        S[ni][2] = __expf(S[ni][2] - mx1);
        S[ni][3] = __expf(S[ni][3] - mx1);
        sm0 += S[ni][0] + S[ni][1];
        sm1 += S[ni][2] + S[ni][3];
    }
#pragma unroll
    for (int x = 1; x <= 2; x <<= 1) {
        sm0 += __shfl_xor_sync(0xffffffffu, sm0, x);
        sm1 += __shfl_xor_sync(0xffffffffu, sm1, x);
    }

    // ---- Y = P V  (P fragments assembled from S registers) ----
    float Y[4][4];
#pragma unroll
    for (int nj = 0; nj < 4; nj++)
#pragma unroll
        for (int rr = 0; rr < 4; rr++) Y[nj][rr] = 0.f;

#pragma unroll
    for (int kk = 0; kk < 8; kk++) {
        uint32_t ph[4], pl[4];
        split2(S[2 * kk][0],     S[2 * kk][1],     ph[0], pl[0]);
        split2(S[2 * kk][2],     S[2 * kk][3],     ph[1], pl[1]);
        split2(S[2 * kk + 1][0], S[2 * kk + 1][1], ph[2], pl[2]);
        split2(S[2 * kk + 1][2], S[2 * kk + 1][3], ph[3], pl[3]);
#pragma unroll
        for (int njp = 0; njp < 2; njp++) {
            int vrow = njp * 16 + (quad >> 1) * 8 + rrow;
            uint32_t off = vrow * 272 + kk * 32 + (quad & 1) * 16;
            uint32_t bvh[4], bvl[4];
            ldsm4(bvh, sb + SVH + off);      // {b0,b1}=nj_even, {b2,b3}=nj_odd
            ldsm4(bvl, sb + SVL + off);
            mma16816(Y[2 * njp],     ph, bvh);
            mma16816(Y[2 * njp],     ph, bvl);
            mma16816(Y[2 * njp],     pl, bvh);
            mma16816(Y[2 * njp + 1], ph, bvh + 2);
            mma16816(Y[2 * njp + 1], ph, bvl + 2);
            mma16816(Y[2 * njp + 1], pl, bvh + 2);
        }
    }

    // ---- epilogue: normalize, split once to bf16 hi/lo, scatter to ORIGINAL order ----
    float i0 = 1.0f / sm0, i1 = 1.0f / sm1;
    int row0 = w * 16 + gq;
    size_t off0 = ((size_t)(b * N) + toks[row0]) * C + head * D;
    size_t off1 = ((size_t)(b * N) + toks[row0 + 8]) * C + head * D;
#pragma unroll
    for (int nj = 0; nj < 4; nj++) {
        uint32_t hh, ll;
        split2(Y[nj][0] * i0, Y[nj][1] * i0, hh, ll);
        *(uint32_t*)(g_yh + off0 + nj * 8 + 2 * t) = hh;
        *(uint32_t*)(g_yl + off0 + nj * 8 + 2 * t) = ll;
        split2(Y[nj][2] * i1, Y[nj][3] * i1, hh, ll);
        *(uint32_t*)(g_yh + off1 + nj * 8 + 2 * t) = hh;
        *(uint32_t*)(g_yl + off1 + nj * 8 + 2 * t) = ll;
    }
}

// ---------------- K5: projection GEMM via warp MMA (bf16 3-term split) -------
// R7-proven config: block 128(M) x 64(N), 8 warps (4m x 2n), warp tile 32x32.
// Inputs are pre-split bf16 (g_yh/g_yl, g_wh/g_wl) -> fill phase is pure copy.
#define PM 128
#define PN 64
#define PKC 64
#define PSTR 72                 // bf16 elements per smem row (144 B)
#define SA_HI 0
#define SA_LO (PM * PSTR * 2)
#define SB_HI (SA_LO + PM * PSTR * 2)
#define SB_LO (SB_HI + PN * PSTR * 2)
#define SM_PROJ (SB_LO + PN * PSTR * 2)   // 55296 B

__global__ void __launch_bounds__(256)
k_proj_mma(const float* __restrict__ bias, float* __restrict__ out) {
    extern __shared__ char sm[];
    int tid = threadIdx.x;
    int wid = tid >> 5, lane = tid & 31;
    int g = lane >> 2, t = lane & 3;
    int wm = wid >> 1, wn = wid & 1;          // 4 x 2 warp grid
    int m0 = blockIdx.y * PM, n0 = blockIdx.x * PN;

    const uint32_t* Ah = (const uint32_t*)(sm + SA_HI);
    const uint32_t* Al = (const uint32_t*)(sm + SA_LO);
    const uint32_t* Bh = (const uint32_t*)(sm + SB_HI);
    const uint32_t* Bl = (const uint32_t*)(sm + SB_LO);
    const int RS = PSTR / 2;                  // 36 words per row

    float acc[2][4][4];
#pragma unroll
    for (int mi = 0; mi < 2; mi++)
#pragma unroll
        for (int ni = 0; ni < 4; ni++)
#pragma unroll
            for (int r = 0; r < 4; r++) acc[mi][ni][r] = 0.f;

    for (int ch = 0; ch < C / PKC; ch++) {
        // ---- fill: plain bf16 copies, zero conversion math ----
#pragma unroll 2
        for (int i = tid; i < PM * (PKC / 4); i += 256) {   // 2048 uint2-pairs
            int r = i >> 4, c4 = i & 15;
            size_t src = (size_t)(m0 + r) * C + ch * PKC + c4 * 4;
            int off = r * (PSTR * 2) + c4 * 8;
            *(uint2*)(sm + SA_HI + off) = *(const uint2*)(g_yh + src);
            *(uint2*)(sm + SA_LO + off) = *(const uint2*)(g_yl + src);
        }
#pragma unroll 2
        for (int i = tid; i < PN * (PKC / 4); i += 256) {   // 1024
            int r = i >> 4, c4 = i & 15;
            size_t src = (size_t)(n0 + r) * C + ch * PKC + c4 * 4;
            int off = r * (PSTR * 2) + c4 * 8;
            *(uint2*)(sm + SB_HI + off) = *(const uint2*)(g_wh + src);
            *(uint2*)(sm + SB_LO + off) = *(const uint2*)(g_wl + src);
        }
        __syncthreads();

#pragma unroll
        for (int ksi = 0; ksi < PKC / 16; ksi++) {
            int kw = ksi * 8 + t;

            uint32_t ah[2][4], al[2][4];
#pragma unroll
            for (int mi = 0; mi < 2; mi++) {
                int rb = (wm * 32 + mi * 16 + g) * RS + kw;
                ah[mi][0] = Ah[rb];              al[mi][0] = Al[rb];
                ah[mi][1] = Ah[rb + 8 * RS];     al[mi][1] = Al[rb + 8 * RS];
                ah[mi][2] = Ah[rb + 4];          al[mi][2] = Al[rb + 4];
                ah[mi][3] = Ah[rb + 8 * RS + 4]; al[mi][3] = Al[rb + 8 * RS + 4];
            }
            uint32_t bh[4][2], bl[4][2];
#pragma unroll
            for (int ni = 0; ni < 4; ni++) {
                int rb = (wn * 32 + ni * 8 + g) * RS + kw;
                bh[ni][0] = Bh[rb];     bl[ni][0] = Bl[rb];
                bh[ni][1] = Bh[rb + 4]; bl[ni][1] = Bl[rb + 4];
            }
#pragma unroll
            for (int mi = 0; mi < 2; mi++)
#pragma unroll
                for (int ni = 0; ni < 4; ni++) {
                    mma16816(acc[mi][ni], ah[mi], bh[ni]);   // hh
                    mma16816(acc[mi][ni], ah[mi], bl[ni]);   // hl
                    mma16816(acc[mi][ni], al[mi], bh[ni]);   // lh
                }
        }
        __syncthreads();
    }

#pragma unroll
    for (int ni = 0; ni < 4; ni++) {
        int cn = n0 + wn * 32 + ni * 8 + t * 2;
        float2 bb = *(const float2*)(bias + cn);
#pragma unroll
        for (int mi = 0; mi < 2; mi++) {
            int r0 = m0 + wm * 32 + mi * 16 + g;
            float2 o0, o1;
            o0.x = acc[mi][ni][0] + bb.x;
            o0.y = acc[mi][ni][1] + bb.y;
            o1.x = acc[mi][ni][2] + bb.x;
            o1.y = acc[mi][ni][3] + bb.y;
            *(float2*)(out + (size_t)r0 * C + cn)       = o0;
            *(float2*)(out + (size_t)(r0 + 8) * C + cn) = o1;
        }
    }
}

// ---------------- launch ----------------
extern "C" void kernel_launch(void* const* d_in, const int* in_sizes, int n_in,
                              void* d_out, int out_size) {
    const float* qkv  = (const float*)d_in[0];
    const float* sim  = (const float*)d_in[1];
    const float* W    = (const float*)d_in[2];
    const float* bias = (const float*)d_in[3];
    const float* ls   = (const float*)d_in[4];
    float* out = (float*)d_out;

    cudaFuncSetAttribute(k_attn_mma, cudaFuncAttributeMaxDynamicSharedMemorySize,
                         SM_ATTN);
    cudaFuncSetAttribute(k_proj_mma, cudaFuncAttributeMaxDynamicSharedMemorySize,
                         SM_PROJ);

    k_wsplit<<<C * C / 1024, 256>>>(W);
    k_argmax_count<<<dim3(NCH, B), CHUNK>>>(sim);
    k_scan<<<B, 1024>>>();
    k_scatter<<<dim3(NCH, B), CHUNK>>>();
    k_attn_mma<<<dim3(HDS, NG, B), 256, SM_ATTN>>>(qkv, ls);
    k_proj_mma<<<dim3(C / PN, (B * N) / PM), 256, SM_PROJ>>>(bias, out);
}

// round 11
// speedup vs baseline: 1.1420x; 1.1420x over previous
#include <cuda_runtime.h>
#include <cuda_bf16.h>
#include <math.h>
#include <cstdint>

// Problem constants (fixed by the dataset)
#define B    4
#define N    16384
#define C    256
#define C3   768
#define T    64        // categories
#define HDS  8
#define D    32        // head dim
#define GS   128       // group size
#define NG   128       // groups per batch
#define CHUNK 128
#define NCH   128      // N / CHUNK

// ---------------- scratch (static device allocations only) ----------------
__device__ int   g_tkid[B * N];
__device__ int   g_counts[B * T * NCH];     // [b][key][chunk], scanned in place
__device__ int   g_sortidx[B * N];          // sorted position -> original token
// attention output in ORIGINAL token order, pre-split bf16 hi/lo
__device__ __nv_bfloat16 g_yh[(size_t)B * N * C];
__device__ __nv_bfloat16 g_yl[(size_t)B * N * C];
// pre-split projection weight
__device__ __nv_bfloat16 g_wh[C * C];
__device__ __nv_bfloat16 g_wl[C * C];

// bf16 hi/lo split of a pair of floats, packed as bf16x2 words
__device__ __forceinline__ void split2(float a, float b, uint32_t& hi, uint32_t& lo) {
    __nv_bfloat162 h = __floats2bfloat162_rn(a, b);
    float ra = a - __bfloat162float(h.x);
    float rb = b - __bfloat162float(h.y);
    __nv_bfloat162 l = __floats2bfloat162_rn(ra, rb);
    hi = *(uint32_t*)&h;
    lo = *(uint32_t*)&l;
}

// warp-level bf16 MMA, fp32 accumulate (sm_80+, no arch-feature gate)
__device__ __forceinline__ void mma16816(float* c, const uint32_t* a, const uint32_t* b) {
    asm volatile(
        "mma.sync.aligned.m16n8k16.row.col.f32.bf16.bf16.f32 "
        "{%0,%1,%2,%3}, {%4,%5,%6,%7}, {%8,%9}, {%0,%1,%2,%3};"
        : "+f"(c[0]), "+f"(c[1]), "+f"(c[2]), "+f"(c[3])
        : "r"(a[0]), "r"(a[1]), "r"(a[2]), "r"(a[3]), "r"(b[0]), "r"(b[1]));
}

__device__ __forceinline__ uint32_t smem_u32(const void* p) {
    uint32_t a;
    asm("{ .reg .u64 t; cvta.to.shared.u64 t, %1; cvt.u32.u64 %0, t; }"
        : "=r"(a) : "l"(p));
    return a;
}
__device__ __forceinline__ void ldsm4(uint32_t* r, uint32_t addr) {
    asm volatile("ldmatrix.sync.aligned.m8n8.x4.shared.b16 {%0,%1,%2,%3}, [%4];"
                 : "=r"(r[0]), "=r"(r[1]), "=r"(r[2]), "=r"(r[3]) : "r"(addr));
}
__device__ __forceinline__ void cp16(uint32_t dst, const void* src) {
    asm volatile("cp.async.cg.shared.global [%0], [%1], 16;"
                 :: "r"(dst), "l"(src) : "memory");
}

// ---------------- K0: pre-split W into bf16 hi/lo (runs once per launch) -----
__global__ void k_wsplit(const float* __restrict__ W) {
    int i = blockIdx.x * 256 + threadIdx.x;   // 16384 float4s
    float4 v = ((const float4*)W)[i];
    uint32_t h0, l0, h1, l1;
    split2(v.x, v.y, h0, l0);
    split2(v.z, v.w, h1, l1);
    *(uint2*)(g_wh + i * 4) = make_uint2(h0, h1);
    *(uint2*)(g_wl + i * 4) = make_uint2(l0, l1);
}

// ---------------- K1: per-token argmax + per-chunk histogram ----------------
__global__ void k_argmax_count(const float* __restrict__ sim) {
    int b = blockIdx.y, ch = blockIdx.x, tid = threadIdx.x;
    __shared__ float ss[CHUNK * T];   // 32 KB
    __shared__ int   hist[T];

    const float4* src = (const float4*)(sim + ((size_t)(b * N + ch * CHUNK)) * T);
    float4* dst = (float4*)ss;
#pragma unroll
    for (int i = tid; i < CHUNK * T / 4; i += CHUNK) dst[i] = src[i];
    if (tid < T) hist[tid] = 0;
    __syncthreads();

    const float* row = ss + tid * T;
    float best = row[0];
    int   bi   = 0;
#pragma unroll
    for (int j = 1; j < T; j++) {
        float v = row[j];
        if (v > best) { best = v; bi = j; }   // first-max == jnp.argmax tie rule
    }
    g_tkid[b * N + ch * CHUNK + tid] = bi;
    atomicAdd(&hist[bi], 1);
    __syncthreads();
    if (tid < T) g_counts[(b * T + tid) * NCH + ch] = hist[tid];
}

// ---------------- K2: per-batch exclusive scan of counts (8192 ints) ----------------
__global__ void k_scan() {
    const int PER = (T * NCH) / 1024;   // 8
    int b = blockIdx.x, tid = threadIdx.x;
    __shared__ int t1[1024], t2[1024];
    int* cnt = g_counts + b * T * NCH;

    int v[PER];
    int s = 0;
#pragma unroll
    for (int i = 0; i < PER; i++) { v[i] = cnt[tid * PER + i]; s += v[i]; }
    t1[tid] = s;
    __syncthreads();

    int* a  = t1;
    int* bb = t2;
    for (int off = 1; off < 1024; off <<= 1) {
        int x = a[tid];
        if (tid >= off) x += a[tid - off];
        bb[tid] = x;
        __syncthreads();
        int* tmp = a; a = bb; bb = tmp;
    }
    int pre = (tid == 0) ? 0 : a[tid - 1];
#pragma unroll
    for (int i = 0; i < PER; i++) { cnt[tid * PER + i] = pre; pre += v[i]; }
}

// ---------------- K3: stable scatter (match_any rank, no serial loop) --------
__global__ void k_scatter() {
    int b = blockIdx.y, ch = blockIdx.x, tid = threadIdx.x;
    __shared__ int wcnt[4][T];
    int w = tid >> 5, lane = tid & 31;
    for (int i = tid; i < 4 * T; i += CHUNK) ((int*)wcnt)[i] = 0;
    __syncthreads();

    int token = ch * CHUNK + tid;
    int key   = g_tkid[b * N + token];
    unsigned mask  = __match_any_sync(0xffffffffu, key);
    int lrank  = __popc(mask & ((1u << lane) - 1));
    int leader = __ffs(mask) - 1;
    if (lane == leader) wcnt[w][key] = __popc(mask);
    __syncthreads();

    int rank = lrank;
#pragma unroll
    for (int ww = 0; ww < 4; ww++)
        if (ww < w) rank += wcnt[ww][key];
    int pos = g_counts[(b * T + key) * NCH + ch] + rank;
    g_sortidx[b * N + pos] = token;
}

// ---------------- K4: grouped attention via warp MMA (bf16 3-term split) -----
// One CTA (256 thr / 8 warps) per (head, group, batch); warp owns 16 q-rows.
// Q,K smem rows padded to 40 bf16 (80 B): ldmatrix conflict-free.
// V transposed Vt[dim][key], rows 136 bf16 (68 words, 68%32=4) -> conflict-free.
#define ATP 40
#define VTP 136
#define SQH 0
#define SQL (SQH + GS * ATP * 2)          // 10240 each
#define SKH (SQL + GS * ATP * 2)
#define SKL (SKH + GS * ATP * 2)
#define SVH (SKL + GS * ATP * 2)          // Vt: 32*272 = 8704 each
#define SVL (SVH + D * VTP * 2)
#define STOK (SVL + D * VTP * 2)
#define SM_ATTN (STOK + GS * 4)           // 58,880 B

__global__ void __launch_bounds__(256, 2)
k_attn_mma(const float* __restrict__ qkv, const float* __restrict__ logit_scale) {
    extern __shared__ char sm[];
    uint32_t sb = smem_u32(sm);
    int head = blockIdx.x, g = blockIdx.y, b = blockIdx.z;
    int tid = threadIdx.x;
    int* toks = (int*)(sm + STOK);

    int r = tid >> 1, h = tid & 1;           // 2 threads per token row
    int token = g_sortidx[b * N + g * GS + r];
    if (h == 0) toks[r] = token;

    float scale = __expf(fminf(logit_scale[0], 4.6051701859880914f));  // log(100)

    // ---- gather: split q (pre-scaled), k into smem; v transposed ----
    const float4* base =
        (const float4*)(qkv + ((size_t)(b * N) + token) * C3 + head * D);
#pragma unroll
    for (int p = h * 4; p < h * 4 + 4; p += 2) {   // q: 2 float4 pairs
        float4 v0 = base[p], v1 = base[p + 1];
        v0.x *= scale; v0.y *= scale; v0.z *= scale; v0.w *= scale;
        v1.x *= scale; v1.y *= scale; v1.z *= scale; v1.w *= scale;
        uint32_t h0, l0, h1, l1, h2, l2, h3, l3;
        split2(v0.x, v0.y, h0, l0); split2(v0.z, v0.w, h1, l1);
        split2(v1.x, v1.y, h2, l2); split2(v1.z, v1.w, h3, l3);
        *(uint2*)(sm + SQH + r * (ATP * 2) + p * 8)     = make_uint2(h0, h1);
        *(uint2*)(sm + SQH + r * (ATP * 2) + p * 8 + 8) = make_uint2(h2, h3);
        *(uint2*)(sm + SQL + r * (ATP * 2) + p * 8)     = make_uint2(l0, l1);
        *(uint2*)(sm + SQL + r * (ATP * 2) + p * 8 + 8) = make_uint2(l2, l3);
    }
#pragma unroll
    for (int p = h * 4; p < h * 4 + 4; p += 2) {   // k (+256 floats = +64 float4)
        float4 v0 = base[64 + p], v1 = base[64 + p + 1];
        uint32_t h0, l0, h1, l1, h2, l2, h3, l3;
        split2(v0.x, v0.y, h0, l0); split2(v0.z, v0.w, h1, l1);
        split2(v1.x, v1.y, h2, l2); split2(v1.z, v1.w, h3, l3);
        *(uint2*)(sm + SKH + r * (ATP * 2) + p * 8)     = make_uint2(h0, h1);
        *(uint2*)(sm + SKH + r * (ATP * 2) + p * 8 + 8) = make_uint2(h2, h3);
        *(uint2*)(sm + SKL + r * (ATP * 2) + p * 8)     = make_uint2(l0, l1);
        *(uint2*)(sm + SKL + r * (ATP * 2) + p * 8 + 8) = make_uint2(l2, l3);
    }
    {
        __nv_bfloat16* vh = (__nv_bfloat16*)(sm + SVH);
        __nv_bfloat16* vl = (__nv_bfloat16*)(sm + SVL);
#pragma unroll
        for (int p = h * 4; p < h * 4 + 4; p++) {  // v (+512 floats = +128 float4)
            float4 v = base[128 + p];
            uint32_t h0, l0, h1, l1;
            split2(v.x, v.y, h0, l0);
            split2(v.z, v.w, h1, l1);
            __nv_bfloat162 H0 = *(__nv_bfloat162*)&h0, L0 = *(__nv_bfloat162*)&l0;
            __nv_bfloat162 H1 = *(__nv_bfloat162*)&h1, L1 = *(__nv_bfloat162*)&l1;
            int d0 = p * 4;
            vh[(d0 + 0) * VTP + r] = H0.x;  vl[(d0 + 0) * VTP + r] = L0.x;
            vh[(d0 + 1) * VTP + r] = H0.y;  vl[(d0 + 1) * VTP + r] = L0.y;
            vh[(d0 + 2) * VTP + r] = H1.x;  vl[(d0 + 2) * VTP + r] = L1.x;
            vh[(d0 + 3) * VTP + r] = H1.y;  vl[(d0 + 3) * VTP + r] = L1.y;
        }
    }
    __syncthreads();

    int w = tid >> 5, lane = tid & 31;
    int gq = lane >> 2, t = lane & 3;
    int quad = lane >> 3, rrow = lane & 7;   // ldmatrix lane decomposition

    // ---- Q fragments via ldmatrix.x4 (A-operand, 16 rows x k16 per ki) ----
    uint32_t qh[2][4], ql[2][4];
    {
        int qrow = w * 16 + (quad & 1) * 8 + rrow;
#pragma unroll
        for (int ki = 0; ki < 2; ki++) {
            uint32_t off = qrow * 80 + ki * 32 + (quad >> 1) * 16;
            ldsm4(qh[ki], sb + SQH + off);
            ldsm4(ql[ki], sb + SQL + off);
        }
    }

    // ---- S = (scale*Q) K^T, 16x128 per warp in registers ----
    float S[16][4];
#pragma unroll
    for (int ni = 0; ni < 16; ni++)
#pragma unroll
        for (int rr = 0; rr < 4; rr++) S[ni][rr] = 0.f;

#pragma unroll
    for (int np = 0; np < 8; np++) {         // pairs of 8-key B tiles
        int krow = np * 16 + (quad >> 1) * 8 + rrow;
#pragma unroll
        for (int ki = 0; ki < 2; ki++) {
            uint32_t off = krow * 80 + ki * 32 + (quad & 1) * 16;
            uint32_t bh[4], bl[4];
            ldsm4(bh, sb + SKH + off);       // {b0,b1}=ni_even, {b2,b3}=ni_odd
            ldsm4(bl, sb + SKL + off);
            mma16816(S[2 * np],     qh[ki], bh);
            mma16816(S[2 * np],     qh[ki], bl);
            mma16816(S[2 * np],     ql[ki], bh);
            mma16816(S[2 * np + 1], qh[ki], bh + 2);
            mma16816(S[2 * np + 1], qh[ki], bl + 2);
            mma16816(S[2 * np + 1], ql[ki], bh + 2);
        }
    }

    // ---- softmax (two-pass, quad-shuffle row reductions) ----
    float mx0 = -INFINITY, mx1 = -INFINITY;
#pragma unroll
    for (int ni = 0; ni < 16; ni++) {
        mx0 = fmaxf(mx0, fmaxf(S[ni][0], S[ni][1]));
        mx1 = fmaxf(mx1, fmaxf(S[ni][2], S[ni][3]));
    }
#pragma unroll
    for (int x = 1; x <= 2; x <<= 1) {
        mx0 = fmaxf(mx0, __shfl_xor_sync(0xffffffffu, mx0, x));
        mx1 = fmaxf(mx1, __shfl_xor_sync(0xffffffffu, mx1, x));
    }

    float sm0 = 0.f, sm1 = 0.f;
#pragma unroll
    for (int ni = 0; ni < 16; ni++) {
        S[ni][0] = __expf(S[ni][0] - mx0);
        S[ni][1] = __expf(S[ni][1] - mx0);
        S[ni][2] = __expf(S[ni][2] - mx1);
        S[ni][3] = __expf(S[ni][3] - mx1);
        sm0 += S[ni][0] + S[ni][1];
        sm1 += S[ni][2] + S[ni][3];
    }
#pragma unroll
    for (int x = 1; x <= 2; x <<= 1) {
        sm0 += __shfl_xor_sync(0xffffffffu, sm0, x);
        sm1 += __shfl_xor_sync(0xffffffffu, sm1, x);
    }

    // ---- Y = P V  (P fragments assembled from S registers) ----
    float Y[4][4];
#pragma unroll
    for (int nj = 0; nj < 4; nj++)
#pragma unroll
        for (int rr = 0; rr < 4; rr++) Y[nj][rr] = 0.f;

#pragma unroll
    for (int kk = 0; kk < 8; kk++) {
        uint32_t ph[4], pl[4];
        split2(S[2 * kk][0],     S[2 * kk][1],     ph[0], pl[0]);
        split2(S[2 * kk][2],     S[2 * kk][3],     ph[1], pl[1]);
        split2(S[2 * kk + 1][0], S[2 * kk + 1][1], ph[2], pl[2]);
        split2(S[2 * kk + 1][2], S[2 * kk + 1][3], ph[3], pl[3]);
#pragma unroll
        for (int njp = 0; njp < 2; njp++) {
            int vrow = njp * 16 + (quad >> 1) * 8 + rrow;
            uint32_t off = vrow * 272 + kk * 32 + (quad & 1) * 16;
            uint32_t bvh[4], bvl[4];
            ldsm4(bvh, sb + SVH + off);      // {b0,b1}=nj_even, {b2,b3}=nj_odd
            ldsm4(bvl, sb + SVL + off);
            mma16816(Y[2 * njp],     ph, bvh);
            mma16816(Y[2 * njp],     ph, bvl);
            mma16816(Y[2 * njp],     pl, bvh);
            mma16816(Y[2 * njp + 1], ph, bvh + 2);
            mma16816(Y[2 * njp + 1], ph, bvl + 2);
            mma16816(Y[2 * njp + 1], pl, bvh + 2);
        }
    }

    // ---- epilogue: normalize, split once to bf16 hi/lo, scatter to ORIGINAL order ----
    float i0 = 1.0f / sm0, i1 = 1.0f / sm1;
    int row0 = w * 16 + gq;
    size_t off0 = ((size_t)(b * N) + toks[row0]) * C + head * D;
    size_t off1 = ((size_t)(b * N) + toks[row0 + 8]) * C + head * D;
#pragma unroll
    for (int nj = 0; nj < 4; nj++) {
        uint32_t hh, ll;
        split2(Y[nj][0] * i0, Y[nj][1] * i0, hh, ll);
        *(uint32_t*)(g_yh + off0 + nj * 8 + 2 * t) = hh;
        *(uint32_t*)(g_yl + off0 + nj * 8 + 2 * t) = ll;
        split2(Y[nj][2] * i1, Y[nj][3] * i1, hh, ll);
        *(uint32_t*)(g_yh + off1 + nj * 8 + 2 * t) = hh;
        *(uint32_t*)(g_yl + off1 + nj * 8 + 2 * t) = ll;
    }
}

// ---------------- K5: projection GEMM via warp MMA (bf16 3-term split) -------
// Block 128(M) x 64(N), 8 warps (4m x 2n), warp tile 32x32.
// Double-buffered cp.async pipeline: fill chunk ch+1 overlaps MMA of chunk ch.
#define PM 128
#define PN 64
#define PKC 64
#define PSTR 72                 // bf16 elements per smem row (144 B)
#define SA_HI 0
#define SA_LO (PM * PSTR * 2)
#define SB_HI (SA_LO + PM * PSTR * 2)
#define SB_LO (SB_HI + PN * PSTR * 2)
#define SM_BUF (SB_LO + PN * PSTR * 2)    // 55296 B per buffer
#define SM_PROJ (2 * SM_BUF)              // 110592 B

__global__ void __launch_bounds__(256)
k_proj_mma(const float* __restrict__ bias, float* __restrict__ out) {
    extern __shared__ char sm[];
    uint32_t sb = smem_u32(sm);
    int tid = threadIdx.x;
    int wid = tid >> 5, lane = tid & 31;
    int g = lane >> 2, t = lane & 3;
    int wm = wid >> 1, wn = wid & 1;          // 4 x 2 warp grid
    int m0 = blockIdx.y * PM, n0 = blockIdx.x * PN;
    const int RS = PSTR / 2;                  // 36 words per row

    // async fill of one chunk into buffer at byte offset `boff`
    auto fill = [&](int ch, uint32_t boff) {
        uint32_t bA = sb + boff;
#pragma unroll
        for (int i = tid; i < PM * (PKC / 8); i += 256) {   // 1024 segs, 4 iters
            int r = i >> 3, s = i & 7;
            size_t src = (size_t)(m0 + r) * C + ch * PKC + s * 8;
            uint32_t off = (uint32_t)(r * (PSTR * 2) + s * 16);
            cp16(bA + SA_HI + off, g_yh + src);
            cp16(bA + SA_LO + off, g_yl + src);
        }
#pragma unroll
        for (int i = tid; i < PN * (PKC / 8); i += 256) {   // 512 segs, 2 iters
            int r = i >> 3, s = i & 7;
            size_t src = (size_t)(n0 + r) * C + ch * PKC + s * 8;
            uint32_t off = (uint32_t)(r * (PSTR * 2) + s * 16);
            cp16(bA + SB_HI + off, g_wh + src);
            cp16(bA + SB_LO + off, g_wl + src);
        }
        asm volatile("cp.async.commit_group;" ::: "memory");
    };

    float acc[2][4][4];
#pragma unroll
    for (int mi = 0; mi < 2; mi++)
#pragma unroll
        for (int ni = 0; ni < 4; ni++)
#pragma unroll
            for (int r = 0; r < 4; r++) acc[mi][ni][r] = 0.f;

    fill(0, 0);
    int cur = 0;

#pragma unroll
    for (int ch = 0; ch < C / PKC; ch++) {
        if (ch < C / PKC - 1) {
            fill(ch + 1, (uint32_t)((cur ^ 1) * SM_BUF));
            asm volatile("cp.async.wait_group 1;" ::: "memory");
        } else {
            asm volatile("cp.async.wait_group 0;" ::: "memory");
        }
        __syncthreads();

        const char* bufc = sm + cur * SM_BUF;
        const uint32_t* Ah = (const uint32_t*)(bufc + SA_HI);
        const uint32_t* Al = (const uint32_t*)(bufc + SA_LO);
        const uint32_t* Bh = (const uint32_t*)(bufc + SB_HI);
        const uint32_t* Bl = (const uint32_t*)(bufc + SB_LO);

#pragma unroll
        for (int ksi = 0; ksi < PKC / 16; ksi++) {
            int kw = ksi * 8 + t;

            uint32_t ah[2][4], al[2][4];
#pragma unroll
            for (int mi = 0; mi < 2; mi++) {
                int rb = (wm * 32 + mi * 16 + g) * RS + kw;
                ah[mi][0] = Ah[rb];              al[mi][0] = Al[rb];
                ah[mi][1] = Ah[rb + 8 * RS];     al[mi][1] = Al[rb + 8 * RS];
                ah[mi][2] = Ah[rb + 4];          al[mi][2] = Al[rb + 4];
                ah[mi][3] = Ah[rb + 8 * RS + 4]; al[mi][3] = Al[rb + 8 * RS + 4];
            }
            uint32_t bh[4][2], bl[4][2];
#pragma unroll
            for (int ni = 0; ni < 4; ni++) {
                int rb = (wn * 32 + ni * 8 + g) * RS + kw;
                bh[ni][0] = Bh[rb];     bl[ni][0] = Bl[rb];
                bh[ni][1] = Bh[rb + 4]; bl[ni][1] = Bl[rb + 4];
            }
#pragma unroll
            for (int mi = 0; mi < 2; mi++)
#pragma unroll
                for (int ni = 0; ni < 4; ni++) {
                    mma16816(acc[mi][ni], ah[mi], bh[ni]);   // hh
                    mma16816(acc[mi][ni], ah[mi], bl[ni]);   // hl
                    mma16816(acc[mi][ni], al[mi], bh[ni]);   // lh
                }
        }
        __syncthreads();   // MMA reads done before this buffer is refilled
        cur ^= 1;
    }

#pragma unroll
    for (int ni = 0; ni < 4; ni++) {
        int cn = n0 + wn * 32 + ni * 8 + t * 2;
        float2 bb = *(const float2*)(bias + cn);
#pragma unroll
        for (int mi = 0; mi < 2; mi++) {
            int r0 = m0 + wm * 32 + mi * 16 + g;
            float2 o0, o1;
            o0.x = acc[mi][ni][0] + bb.x;
            o0.y = acc[mi][ni][1] + bb.y;
            o1.x = acc[mi][ni][2] + bb.x;
            o1.y = acc[mi][ni][3] + bb.y;
            *(float2*)(out + (size_t)r0 * C + cn)       = o0;
            *(float2*)(out + (size_t)(r0 + 8) * C + cn) = o1;
        }
    }
}

// ---------------- launch ----------------
extern "C" void kernel_launch(void* const* d_in, const int* in_sizes, int n_in,
                              void* d_out, int out_size) {
    const float* qkv  = (const float*)d_in[0];
    const float* sim  = (const float*)d_in[1];
    const float* W    = (const float*)d_in[2];
    const float* bias = (const float*)d_in[3];
    const float* ls   = (const float*)d_in[4];
    float* out = (float*)d_out;

    cudaFuncSetAttribute(k_attn_mma, cudaFuncAttributeMaxDynamicSharedMemorySize,
                         SM_ATTN);
    cudaFuncSetAttribute(k_proj_mma, cudaFuncAttributeMaxDynamicSharedMemorySize,
                         SM_PROJ);

    k_wsplit<<<C * C / 1024, 256>>>(W);
    k_argmax_count<<<dim3(NCH, B), CHUNK>>>(sim);
    k_scan<<<B, 1024>>>();
    k_scatter<<<dim3(NCH, B), CHUNK>>>();
    k_attn_mma<<<dim3(HDS, NG, B), 256, SM_ATTN>>>(qkv, ls);
    k_proj_mma<<<dim3(C / PN, (B * N) / PM), 256, SM_PROJ>>>(bias, out);
}

// round 12
// speedup vs baseline: 1.2764x; 1.1176x over previous
#include <cuda_runtime.h>
#include <cuda_bf16.h>
#include <cuda_fp16.h>
#include <math.h>
#include <cstdint>

// Problem constants (fixed by the dataset)
#define B    4
#define N    16384
#define C    256
#define C3   768
#define T    64        // categories
#define HDS  8
#define D    32        // head dim
#define GS   128       // group size
#define NG   128       // groups per batch
#define CHUNK 128
#define NCH   128      // N / CHUNK

// ---------------- scratch (static device allocations only) ----------------
__device__ int   g_tkid[B * N];
__device__ int   g_counts[B * T * NCH];     // [b][key][chunk], scanned in place
__device__ int   g_sortidx[B * N];          // sorted position -> original token
// attention output in ORIGINAL token order, fp16 hi/lo (exact to 2^-22)
__device__ __half g_yh[(size_t)B * N * C];
__device__ __half g_yl[(size_t)B * N * C];
// projection weight, single fp16 (2^-12 rounding)
__device__ __half g_wf[C * C];

// bf16 hi/lo split of a pair of floats, packed as bf16x2 words
__device__ __forceinline__ void split2(float a, float b, uint32_t& hi, uint32_t& lo) {
    __nv_bfloat162 h = __floats2bfloat162_rn(a, b);
    float ra = a - __bfloat162float(h.x);
    float rb = b - __bfloat162float(h.y);
    __nv_bfloat162 l = __floats2bfloat162_rn(ra, rb);
    hi = *(uint32_t*)&h;
    lo = *(uint32_t*)&l;
}
// fp16 hi/lo split (residual exact to ~2^-22)
__device__ __forceinline__ void split2h(float a, float b, uint32_t& hi, uint32_t& lo) {
    __half2 h = __floats2half2_rn(a, b);
    float ra = a - __low2float(h);
    float rb = b - __high2float(h);
    __half2 l = __floats2half2_rn(ra, rb);
    hi = *(uint32_t*)&h;
    lo = *(uint32_t*)&l;
}

// warp-level bf16 MMA, fp32 accumulate
__device__ __forceinline__ void mma16816(float* c, const uint32_t* a, const uint32_t* b) {
    asm volatile(
        "mma.sync.aligned.m16n8k16.row.col.f32.bf16.bf16.f32 "
        "{%0,%1,%2,%3}, {%4,%5,%6,%7}, {%8,%9}, {%0,%1,%2,%3};"
        : "+f"(c[0]), "+f"(c[1]), "+f"(c[2]), "+f"(c[3])
        : "r"(a[0]), "r"(a[1]), "r"(a[2]), "r"(a[3]), "r"(b[0]), "r"(b[1]));
}
// warp-level fp16 MMA, fp32 accumulate
__device__ __forceinline__ void mma16816h(float* c, const uint32_t* a, const uint32_t* b) {
    asm volatile(
        "mma.sync.aligned.m16n8k16.row.col.f32.f16.f16.f32 "
        "{%0,%1,%2,%3}, {%4,%5,%6,%7}, {%8,%9}, {%0,%1,%2,%3};"
        : "+f"(c[0]), "+f"(c[1]), "+f"(c[2]), "+f"(c[3])
        : "r"(a[0]), "r"(a[1]), "r"(a[2]), "r"(a[3]), "r"(b[0]), "r"(b[1]));
}

__device__ __forceinline__ uint32_t smem_u32(const void* p) {
    uint32_t a;
    asm("{ .reg .u64 t; cvta.to.shared.u64 t, %1; cvt.u32.u64 %0, t; }"
        : "=r"(a) : "l"(p));
    return a;
}
__device__ __forceinline__ void ldsm4(uint32_t* r, uint32_t addr) {
    asm volatile("ldmatrix.sync.aligned.m8n8.x4.shared.b16 {%0,%1,%2,%3}, [%4];"
                 : "=r"(r[0]), "=r"(r[1]), "=r"(r[2]), "=r"(r[3]) : "r"(addr));
}
__device__ __forceinline__ void cp16(uint32_t dst, const void* src) {
    asm volatile("cp.async.cg.shared.global [%0], [%1], 16;"
                 :: "r"(dst), "l"(src) : "memory");
}

// ---------------- K0: convert W to fp16 (runs once per launch) -----
__global__ void k_wsplit(const float* __restrict__ W) {
    int i = blockIdx.x * 256 + threadIdx.x;   // 16384 float4s
    float4 v = ((const float4*)W)[i];
    __half2 a = __floats2half2_rn(v.x, v.y);
    __half2 b = __floats2half2_rn(v.z, v.w);
    uint2 o;
    o.x = *(uint32_t*)&a;
    o.y = *(uint32_t*)&b;
    *(uint2*)(g_wf + i * 4) = o;
}

// ---------------- K1: per-token argmax + per-chunk histogram ----------------
__global__ void k_argmax_count(const float* __restrict__ sim) {
    int b = blockIdx.y, ch = blockIdx.x, tid = threadIdx.x;
    __shared__ float ss[CHUNK * T];   // 32 KB
    __shared__ int   hist[T];

    const float4* src = (const float4*)(sim + ((size_t)(b * N + ch * CHUNK)) * T);
    float4* dst = (float4*)ss;
#pragma unroll
    for (int i = tid; i < CHUNK * T / 4; i += CHUNK) dst[i] = src[i];
    if (tid < T) hist[tid] = 0;
    __syncthreads();

    const float* row = ss + tid * T;
    float best = row[0];
    int   bi   = 0;
#pragma unroll
    for (int j = 1; j < T; j++) {
        float v = row[j];
        if (v > best) { best = v; bi = j; }   // first-max == jnp.argmax tie rule
    }
    g_tkid[b * N + ch * CHUNK + tid] = bi;
    atomicAdd(&hist[bi], 1);
    __syncthreads();
    if (tid < T) g_counts[(b * T + tid) * NCH + ch] = hist[tid];
}

// ---------------- K2: per-batch exclusive scan of counts (8192 ints) ----------------
__global__ void k_scan() {
    const int PER = (T * NCH) / 1024;   // 8
    int b = blockIdx.x, tid = threadIdx.x;
    __shared__ int t1[1024], t2[1024];
    int* cnt = g_counts + b * T * NCH;

    int v[PER];
    int s = 0;
#pragma unroll
    for (int i = 0; i < PER; i++) { v[i] = cnt[tid * PER + i]; s += v[i]; }
    t1[tid] = s;
    __syncthreads();

    int* a  = t1;
    int* bb = t2;
    for (int off = 1; off < 1024; off <<= 1) {
        int x = a[tid];
        if (tid >= off) x += a[tid - off];
        bb[tid] = x;
        __syncthreads();
        int* tmp = a; a = bb; bb = tmp;
    }
    int pre = (tid == 0) ? 0 : a[tid - 1];
#pragma unroll
    for (int i = 0; i < PER; i++) { cnt[tid * PER + i] = pre; pre += v[i]; }
}

// ---------------- K3: stable scatter (match_any rank, no serial loop) --------
__global__ void k_scatter() {
    int b = blockIdx.y, ch = blockIdx.x, tid = threadIdx.x;
    __shared__ int wcnt[4][T];
    int w = tid >> 5, lane = tid & 31;
    for (int i = tid; i < 4 * T; i += CHUNK) ((int*)wcnt)[i] = 0;
    __syncthreads();

    int token = ch * CHUNK + tid;
    int key   = g_tkid[b * N + token];
    unsigned mask  = __match_any_sync(0xffffffffu, key);
    int lrank  = __popc(mask & ((1u << lane) - 1));
    int leader = __ffs(mask) - 1;
    if (lane == leader) wcnt[w][key] = __popc(mask);
    __syncthreads();

    int rank = lrank;
#pragma unroll
    for (int ww = 0; ww < 4; ww++)
        if (ww < w) rank += wcnt[ww][key];
    int pos = g_counts[(b * T + key) * NCH + ch] + rank;
    g_sortidx[b * N + pos] = token;
}

// ---------------- K4: grouped attention via warp MMA -------------------------
// QK: bf16 3-term split (unchanged). PV: P fp16 hi/lo x V single fp16 (2 MMAs).
// Q,K smem rows padded to 40 bf16 (80 B): ldmatrix conflict-free.
// V transposed Vt[dim][key] fp16, rows 136 halves (272 B) -> conflict-free.
#define ATP 40
#define VTP 136
#define SQH 0
#define SQL (SQH + GS * ATP * 2)          // 10240 each
#define SKH (SQL + GS * ATP * 2)
#define SKL (SKH + GS * ATP * 2)
#define SVH (SKL + GS * ATP * 2)          // Vt fp16: 32*272 = 8704
#define STOK (SVH + D * VTP * 2)
#define SM_ATTN (STOK + GS * 4)           // 50,176 B

__global__ void __launch_bounds__(256, 2)
k_attn_mma(const float* __restrict__ qkv, const float* __restrict__ logit_scale) {
    extern __shared__ char sm[];
    uint32_t sb = smem_u32(sm);
    int head = blockIdx.x, g = blockIdx.y, b = blockIdx.z;
    int tid = threadIdx.x;
    int* toks = (int*)(sm + STOK);

    int r = tid >> 1, h = tid & 1;           // 2 threads per token row
    int token = g_sortidx[b * N + g * GS + r];
    if (h == 0) toks[r] = token;

    float scale = __expf(fminf(logit_scale[0], 4.6051701859880914f));  // log(100)

    // ---- gather: split q (pre-scaled), k into smem; v transposed fp16 ----
    const float4* base =
        (const float4*)(qkv + ((size_t)(b * N) + token) * C3 + head * D);
#pragma unroll
    for (int p = h * 4; p < h * 4 + 4; p += 2) {   // q: 2 float4 pairs
        float4 v0 = base[p], v1 = base[p + 1];
        v0.x *= scale; v0.y *= scale; v0.z *= scale; v0.w *= scale;
        v1.x *= scale; v1.y *= scale; v1.z *= scale; v1.w *= scale;
        uint32_t h0, l0, h1, l1, h2, l2, h3, l3;
        split2(v0.x, v0.y, h0, l0); split2(v0.z, v0.w, h1, l1);
        split2(v1.x, v1.y, h2, l2); split2(v1.z, v1.w, h3, l3);
        *(uint2*)(sm + SQH + r * (ATP * 2) + p * 8)     = make_uint2(h0, h1);
        *(uint2*)(sm + SQH + r * (ATP * 2) + p * 8 + 8) = make_uint2(h2, h3);
        *(uint2*)(sm + SQL + r * (ATP * 2) + p * 8)     = make_uint2(l0, l1);
        *(uint2*)(sm + SQL + r * (ATP * 2) + p * 8 + 8) = make_uint2(l2, l3);
    }
#pragma unroll
    for (int p = h * 4; p < h * 4 + 4; p += 2) {   // k (+256 floats = +64 float4)
        float4 v0 = base[64 + p], v1 = base[64 + p + 1];
        uint32_t h0, l0, h1, l1, h2, l2, h3, l3;
        split2(v0.x, v0.y, h0, l0); split2(v0.z, v0.w, h1, l1);
        split2(v1.x, v1.y, h2, l2); split2(v1.z, v1.w, h3, l3);
        *(uint2*)(sm + SKH + r * (ATP * 2) + p * 8)     = make_uint2(h0, h1);
        *(uint2*)(sm + SKH + r * (ATP * 2) + p * 8 + 8) = make_uint2(h2, h3);
        *(uint2*)(sm + SKL + r * (ATP * 2) + p * 8)     = make_uint2(l0, l1);
        *(uint2*)(sm + SKL + r * (ATP * 2) + p * 8 + 8) = make_uint2(l2, l3);
    }
    {
        __half* vh = (__half*)(sm + SVH);
#pragma unroll
        for (int p = h * 4; p < h * 4 + 4; p++) {  // v (+512 floats = +128 float4)
            float4 v = base[128 + p];
            __half2 H0 = __floats2half2_rn(v.x, v.y);
            __half2 H1 = __floats2half2_rn(v.z, v.w);
            int d0 = p * 4;
            vh[(d0 + 0) * VTP + r] = H0.x;
            vh[(d0 + 1) * VTP + r] = H0.y;
            vh[(d0 + 2) * VTP + r] = H1.x;
            vh[(d0 + 3) * VTP + r] = H1.y;
        }
    }
    __syncthreads();

    int w = tid >> 5, lane = tid & 31;
    int gq = lane >> 2, t = lane & 3;
    int quad = lane >> 3, rrow = lane & 7;   // ldmatrix lane decomposition

    // ---- Q fragments via ldmatrix.x4 (A-operand, 16 rows x k16 per ki) ----
    uint32_t qh[2][4], ql[2][4];
    {
        int qrow = w * 16 + (quad & 1) * 8 + rrow;
#pragma unroll
        for (int ki = 0; ki < 2; ki++) {
            uint32_t off = qrow * 80 + ki * 32 + (quad >> 1) * 16;
            ldsm4(qh[ki], sb + SQH + off);
            ldsm4(ql[ki], sb + SQL + off);
        }
    }

    // ---- S = (scale*Q) K^T, 16x128 per warp in registers ----
    float S[16][4];
#pragma unroll
    for (int ni = 0; ni < 16; ni++)
#pragma unroll
        for (int rr = 0; rr < 4; rr++) S[ni][rr] = 0.f;

#pragma unroll
    for (int np = 0; np < 8; np++) {         // pairs of 8-key B tiles
        int krow = np * 16 + (quad >> 1) * 8 + rrow;
#pragma unroll
        for (int ki = 0; ki < 2; ki++) {
            uint32_t off = krow * 80 + ki * 32 + (quad & 1) * 16;
            uint32_t bh[4], bl[4];
            ldsm4(bh, sb + SKH + off);       // {b0,b1}=ni_even, {b2,b3}=ni_odd
            ldsm4(bl, sb + SKL + off);
            mma16816(S[2 * np],     qh[ki], bh);
            mma16816(S[2 * np],     qh[ki], bl);
            mma16816(S[2 * np],     ql[ki], bh);
            mma16816(S[2 * np + 1], qh[ki], bh + 2);
            mma16816(S[2 * np + 1], qh[ki], bl + 2);
            mma16816(S[2 * np + 1], ql[ki], bh + 2);
        }
    }

    // ---- softmax (two-pass, quad-shuffle row reductions) ----
    float mx0 = -INFINITY, mx1 = -INFINITY;
#pragma unroll
    for (int ni = 0; ni < 16; ni++) {
        mx0 = fmaxf(mx0, fmaxf(S[ni][0], S[ni][1]));
        mx1 = fmaxf(mx1, fmaxf(S[ni][2], S[ni][3]));
    }
#pragma unroll
    for (int x = 1; x <= 2; x <<= 1) {
        mx0 = fmaxf(mx0, __shfl_xor_sync(0xffffffffu, mx0, x));
        mx1 = fmaxf(mx1, __shfl_xor_sync(0xffffffffu, mx1, x));
    }

    float sm0 = 0.f, sm1 = 0.f;
#pragma unroll
    for (int ni = 0; ni < 16; ni++) {
        S[ni][0] = __expf(S[ni][0] - mx0);
        S[ni][1] = __expf(S[ni][1] - mx0);
        S[ni][2] = __expf(S[ni][2] - mx1);
        S[ni][3] = __expf(S[ni][3] - mx1);
        sm0 += S[ni][0] + S[ni][1];
        sm1 += S[ni][2] + S[ni][3];
    }
#pragma unroll
    for (int x = 1; x <= 2; x <<= 1) {
        sm0 += __shfl_xor_sync(0xffffffffu, sm0, x);
        sm1 += __shfl_xor_sync(0xffffffffu, sm1, x);
    }

    // ---- Y = P V  (P fp16 hi/lo from S registers, V single fp16) ----
    float Y[4][4];
#pragma unroll
    for (int nj = 0; nj < 4; nj++)
#pragma unroll
        for (int rr = 0; rr < 4; rr++) Y[nj][rr] = 0.f;

#pragma unroll
    for (int kk = 0; kk < 8; kk++) {
        uint32_t ph[4], pl[4];
        split2h(S[2 * kk][0],     S[2 * kk][1],     ph[0], pl[0]);
        split2h(S[2 * kk][2],     S[2 * kk][3],     ph[1], pl[1]);
        split2h(S[2 * kk + 1][0], S[2 * kk + 1][1], ph[2], pl[2]);
        split2h(S[2 * kk + 1][2], S[2 * kk + 1][3], ph[3], pl[3]);
#pragma unroll
        for (int njp = 0; njp < 2; njp++) {
            int vrow = njp * 16 + (quad >> 1) * 8 + rrow;
            uint32_t off = vrow * 272 + kk * 32 + (quad & 1) * 16;
            uint32_t bv[4];
            ldsm4(bv, sb + SVH + off);       // {b0,b1}=nj_even, {b2,b3}=nj_odd
            mma16816h(Y[2 * njp],     ph, bv);
            mma16816h(Y[2 * njp],     pl, bv);
            mma16816h(Y[2 * njp + 1], ph, bv + 2);
            mma16816h(Y[2 * njp + 1], pl, bv + 2);
        }
    }

    // ---- epilogue: normalize, fp16 hi/lo split, scatter to ORIGINAL order ----
    float i0 = 1.0f / sm0, i1 = 1.0f / sm1;
    int row0 = w * 16 + gq;
    size_t off0 = ((size_t)(b * N) + toks[row0]) * C + head * D;
    size_t off1 = ((size_t)(b * N) + toks[row0 + 8]) * C + head * D;
#pragma unroll
    for (int nj = 0; nj < 4; nj++) {
        uint32_t hh, ll;
        split2h(Y[nj][0] * i0, Y[nj][1] * i0, hh, ll);
        *(uint32_t*)(g_yh + off0 + nj * 8 + 2 * t) = hh;
        *(uint32_t*)(g_yl + off0 + nj * 8 + 2 * t) = ll;
        split2h(Y[nj][2] * i1, Y[nj][3] * i1, hh, ll);
        *(uint32_t*)(g_yh + off1 + nj * 8 + 2 * t) = hh;
        *(uint32_t*)(g_yl + off1 + nj * 8 + 2 * t) = ll;
    }
}

// ---------------- K5: projection GEMM (y fp16 hi/lo x W single fp16) ---------
// Block 128(M) x 64(N), 8 warps (4m x 2n), warp tile 32x32, 2 MMAs per tile.
// Double-buffered cp.async pipeline.
#define PM 128
#define PN 64
#define PKC 64
#define PSTR 72                 // fp16 elements per smem row (144 B)
#define SA_HI 0
#define SA_LO (PM * PSTR * 2)
#define SB_W  (SA_LO + PM * PSTR * 2)
#define SM_BUF (SB_W + PN * PSTR * 2)     // 46080 B per buffer
#define SM_PROJ (2 * SM_BUF)              // 92160 B

__global__ void __launch_bounds__(256)
k_proj_mma(const float* __restrict__ bias, float* __restrict__ out) {
    extern __shared__ char sm[];
    uint32_t sb = smem_u32(sm);
    int tid = threadIdx.x;
    int wid = tid >> 5, lane = tid & 31;
    int g = lane >> 2, t = lane & 3;
    int wm = wid >> 1, wn = wid & 1;          // 4 x 2 warp grid
    int m0 = blockIdx.y * PM, n0 = blockIdx.x * PN;
    const int RS = PSTR / 2;                  // 36 words per row

    // async fill of one chunk into buffer at byte offset `boff`
    auto fill = [&](int ch, uint32_t boff) {
        uint32_t bA = sb + boff;
#pragma unroll
        for (int i = tid; i < PM * (PKC / 8); i += 256) {   // 1024 segs, 4 iters
            int r = i >> 3, s = i & 7;
            size_t src = (size_t)(m0 + r) * C + ch * PKC + s * 8;
            uint32_t off = (uint32_t)(r * (PSTR * 2) + s * 16);
            cp16(bA + SA_HI + off, g_yh + src);
            cp16(bA + SA_LO + off, g_yl + src);
        }
#pragma unroll
        for (int i = tid; i < PN * (PKC / 8); i += 256) {   // 512 segs, 2 iters
            int r = i >> 3, s = i & 7;
            size_t src = (size_t)(n0 + r) * C + ch * PKC + s * 8;
            uint32_t off = (uint32_t)(r * (PSTR * 2) + s * 16);
            cp16(bA + SB_W + off, g_wf + src);
        }
        asm volatile("cp.async.commit_group;" ::: "memory");
    };

    float acc[2][4][4];
#pragma unroll
    for (int mi = 0; mi < 2; mi++)
#pragma unroll
        for (int ni = 0; ni < 4; ni++)
#pragma unroll
            for (int r = 0; r < 4; r++) acc[mi][ni][r] = 0.f;

    fill(0, 0);
    int cur = 0;

#pragma unroll
    for (int ch = 0; ch < C / PKC; ch++) {
        if (ch < C / PKC - 1) {
            fill(ch + 1, (uint32_t)((cur ^ 1) * SM_BUF));
            asm volatile("cp.async.wait_group 1;" ::: "memory");
        } else {
            asm volatile("cp.async.wait_group 0;" ::: "memory");
        }
        __syncthreads();

        const char* bufc = sm + cur * SM_BUF;
        const uint32_t* Ah = (const uint32_t*)(bufc + SA_HI);
        const uint32_t* Al = (const uint32_t*)(bufc + SA_LO);
        const uint32_t* Bw = (const uint32_t*)(bufc + SB_W);

#pragma unroll
        for (int ksi = 0; ksi < PKC / 16; ksi++) {
            int kw = ksi * 8 + t;

            uint32_t ah[2][4], al[2][4];
#pragma unroll
            for (int mi = 0; mi < 2; mi++) {
                int rb = (wm * 32 + mi * 16 + g) * RS + kw;
                ah[mi][0] = Ah[rb];              al[mi][0] = Al[rb];
                ah[mi][1] = Ah[rb + 8 * RS];     al[mi][1] = Al[rb + 8 * RS];
                ah[mi][2] = Ah[rb + 4];          al[mi][2] = Al[rb + 4];
                ah[mi][3] = Ah[rb + 8 * RS + 4]; al[mi][3] = Al[rb + 8 * RS + 4];
            }
            uint32_t bf[4][2];
#pragma unroll
            for (int ni = 0; ni < 4; ni++) {
                int rb = (wn * 32 + ni * 8 + g) * RS + kw;
                bf[ni][0] = Bw[rb];
                bf[ni][1] = Bw[rb + 4];
            }
#pragma unroll
            for (int mi = 0; mi < 2; mi++)
#pragma unroll
                for (int ni = 0; ni < 4; ni++) {
                    mma16816h(acc[mi][ni], ah[mi], bf[ni]);   // hi term
                    mma16816h(acc[mi][ni], al[mi], bf[ni]);   // lo term
                }
        }
        __syncthreads();   // MMA reads done before this buffer is refilled
        cur ^= 1;
    }

#pragma unroll
    for (int ni = 0; ni < 4; ni++) {
        int cn = n0 + wn * 32 + ni * 8 + t * 2;
        float2 bb = *(const float2*)(bias + cn);
#pragma unroll
        for (int mi = 0; mi < 2; mi++) {
            int r0 = m0 + wm * 32 + mi * 16 + g;
            float2 o0, o1;
            o0.x = acc[mi][ni][0] + bb.x;
            o0.y = acc[mi][ni][1] + bb.y;
            o1.x = acc[mi][ni][2] + bb.x;
            o1.y = acc[mi][ni][3] + bb.y;
            *(float2*)(out + (size_t)r0 * C + cn)       = o0;
            *(float2*)(out + (size_t)(r0 + 8) * C + cn) = o1;
        }
    }
}

// ---------------- launch ----------------
extern "C" void kernel_launch(void* const* d_in, const int* in_sizes, int n_in,
                              void* d_out, int out_size) {
    const float* qkv  = (const float*)d_in[0];
    const float* sim  = (const float*)d_in[1];
    const float* W    = (const float*)d_in[2];
    const float* bias = (const float*)d_in[3];
    const float* ls   = (const float*)d_in[4];
    float* out = (float*)d_out;

    cudaFuncSetAttribute(k_attn_mma, cudaFuncAttributeMaxDynamicSharedMemorySize,
                         SM_ATTN);
    cudaFuncSetAttribute(k_proj_mma, cudaFuncAttributeMaxDynamicSharedMemorySize,
                         SM_PROJ);

    k_wsplit<<<C * C / 1024, 256>>>(W);
    k_argmax_count<<<dim3(NCH, B), CHUNK>>>(sim);
    k_scan<<<B, 1024>>>();
    k_scatter<<<dim3(NCH, B), CHUNK>>>();
    k_attn_mma<<<dim3(HDS, NG, B), 256, SM_ATTN>>>(qkv, ls);
    k_proj_mma<<<dim3(C / PN, (B * N) / PM), 256, SM_PROJ>>>(bias, out);
}

// round 13
// speedup vs baseline: 1.2902x; 1.0108x over previous
#include <cuda_runtime.h>
#include <cuda_bf16.h>
#include <cuda_fp16.h>
#include <math.h>
#include <cstdint>

// Problem constants (fixed by the dataset)
#define B    4
#define N    16384
#define C    256
#define C3   768
#define T    64        // categories
#define HDS  8
#define D    32        // head dim
#define GS   128       // group size
#define NG   128       // groups per batch
#define CHUNK 128
#define NCH   128      // N / CHUNK

// ---------------- scratch (static device allocations only) ----------------
__device__ int   g_tkid[B * N];
__device__ int   g_counts[B * T * NCH];     // [b][key][chunk], scanned in place
__device__ int   g_sortidx[B * N];          // sorted position -> original token
// attention output in ORIGINAL token order, fp16 hi/lo (exact to 2^-22)
__device__ __half g_yh[(size_t)B * N * C];
__device__ __half g_yl[(size_t)B * N * C];
// projection weight, single fp16 (2^-12 rounding)
__device__ __half g_wf[C * C];

// bf16 hi/lo split of a pair of floats, packed as bf16x2 words
__device__ __forceinline__ void split2(float a, float b, uint32_t& hi, uint32_t& lo) {
    __nv_bfloat162 h = __floats2bfloat162_rn(a, b);
    float ra = a - __bfloat162float(h.x);
    float rb = b - __bfloat162float(h.y);
    __nv_bfloat162 l = __floats2bfloat162_rn(ra, rb);
    hi = *(uint32_t*)&h;
    lo = *(uint32_t*)&l;
}
// fp16 hi/lo split (residual exact to ~2^-22)
__device__ __forceinline__ void split2h(float a, float b, uint32_t& hi, uint32_t& lo) {
    __half2 h = __floats2half2_rn(a, b);
    float ra = a - __low2float(h);
    float rb = b - __high2float(h);
    __half2 l = __floats2half2_rn(ra, rb);
    hi = *(uint32_t*)&h;
    lo = *(uint32_t*)&l;
}

// warp-level bf16 MMA, fp32 accumulate
__device__ __forceinline__ void mma16816(float* c, const uint32_t* a, const uint32_t* b) {
    asm volatile(
        "mma.sync.aligned.m16n8k16.row.col.f32.bf16.bf16.f32 "
        "{%0,%1,%2,%3}, {%4,%5,%6,%7}, {%8,%9}, {%0,%1,%2,%3};"
        : "+f"(c[0]), "+f"(c[1]), "+f"(c[2]), "+f"(c[3])
        : "r"(a[0]), "r"(a[1]), "r"(a[2]), "r"(a[3]), "r"(b[0]), "r"(b[1]));
}
// warp-level fp16 MMA, fp32 accumulate
__device__ __forceinline__ void mma16816h(float* c, const uint32_t* a, const uint32_t* b) {
    asm volatile(
        "mma.sync.aligned.m16n8k16.row.col.f32.f16.f16.f32 "
        "{%0,%1,%2,%3}, {%4,%5,%6,%7}, {%8,%9}, {%0,%1,%2,%3};"
        : "+f"(c[0]), "+f"(c[1]), "+f"(c[2]), "+f"(c[3])
        : "r"(a[0]), "r"(a[1]), "r"(a[2]), "r"(a[3]), "r"(b[0]), "r"(b[1]));
}

__device__ __forceinline__ uint32_t smem_u32(const void* p) {
    uint32_t a;
    asm("{ .reg .u64 t; cvta.to.shared.u64 t, %1; cvt.u32.u64 %0, t; }"
        : "=r"(a) : "l"(p));
    return a;
}
__device__ __forceinline__ void ldsm4(uint32_t* r, uint32_t addr) {
    asm volatile("ldmatrix.sync.aligned.m8n8.x4.shared.b16 {%0,%1,%2,%3}, [%4];"
                 : "=r"(r[0]), "=r"(r[1]), "=r"(r[2]), "=r"(r[3]) : "r"(addr));
}
__device__ __forceinline__ void cp16(uint32_t dst, const void* src) {
    asm volatile("cp.async.cg.shared.global [%0], [%1], 16;"
                 :: "r"(dst), "l"(src) : "memory");
}

// ---------------- K1: per-token argmax + per-chunk histogram ----------------
// Staging rows padded to T+1=65 floats: read addr (l*65+j)%32 = (l+j)%32 ->
// conflict-free (the old unpadded layout was a 32-way conflict per iteration).
__global__ void k_argmax_count(const float* __restrict__ sim) {
    int b = blockIdx.y, ch = blockIdx.x, tid = threadIdx.x;
    __shared__ float ss[CHUNK * (T + 1)];   // 33.3 KB
    __shared__ int   hist[T];

    const float4* src = (const float4*)(sim + ((size_t)(b * N + ch * CHUNK)) * T);
#pragma unroll
    for (int i = tid; i < CHUNK * T / 4; i += CHUNK) {
        float4 v = src[i];
        int row = i >> 4, c = (i & 15) * 4;
        float* d = ss + row * (T + 1) + c;
        d[0] = v.x; d[1] = v.y; d[2] = v.z; d[3] = v.w;
    }
    if (tid < T) hist[tid] = 0;
    __syncthreads();

    const float* row = ss + tid * (T + 1);
    float best = row[0];
    int   bi   = 0;
#pragma unroll
    for (int j = 1; j < T; j++) {
        float v = row[j];
        if (v > best) { best = v; bi = j; }   // first-max == jnp.argmax tie rule
    }
    g_tkid[b * N + ch * CHUNK + tid] = bi;
    atomicAdd(&hist[bi], 1);
    __syncthreads();
    if (tid < T) g_counts[(b * T + tid) * NCH + ch] = hist[tid];
}

// ---------------- K2: per-batch exclusive scan of counts + W fp16 convert ----
__global__ void k_scan(const float* __restrict__ W) {
    const int PER = (T * NCH) / 1024;   // 8
    int b = blockIdx.x, tid = threadIdx.x;
    __shared__ int t1[1024], t2[1024];
    int* cnt = g_counts + b * T * NCH;

    // fold in W->fp16 conversion (4 blocks x 1024 thr x 4 float4 = 16384)
#pragma unroll
    for (int j = 0; j < 4; j++) {
        int i = (b * 1024 + tid) * 4 + j;
        float4 v = ((const float4*)W)[i];
        __half2 a = __floats2half2_rn(v.x, v.y);
        __half2 c = __floats2half2_rn(v.z, v.w);
        uint2 o;
        o.x = *(uint32_t*)&a;
        o.y = *(uint32_t*)&c;
        *(uint2*)(g_wf + i * 4) = o;
    }

    int v[PER];
    int s = 0;
#pragma unroll
    for (int i = 0; i < PER; i++) { v[i] = cnt[tid * PER + i]; s += v[i]; }
    t1[tid] = s;
    __syncthreads();

    int* a  = t1;
    int* bb = t2;
    for (int off = 1; off < 1024; off <<= 1) {
        int x = a[tid];
        if (tid >= off) x += a[tid - off];
        bb[tid] = x;
        __syncthreads();
        int* tmp = a; a = bb; bb = tmp;
    }
    int pre = (tid == 0) ? 0 : a[tid - 1];
#pragma unroll
    for (int i = 0; i < PER; i++) { cnt[tid * PER + i] = pre; pre += v[i]; }
}

// ---------------- K3: stable scatter (match_any rank, no serial loop) --------
__global__ void k_scatter() {
    int b = blockIdx.y, ch = blockIdx.x, tid = threadIdx.x;
    __shared__ int wcnt[4][T];
    int w = tid >> 5, lane = tid & 31;
    for (int i = tid; i < 4 * T; i += CHUNK) ((int*)wcnt)[i] = 0;
    __syncthreads();

    int token = ch * CHUNK + tid;
    int key   = g_tkid[b * N + token];
    unsigned mask  = __match_any_sync(0xffffffffu, key);
    int lrank  = __popc(mask & ((1u << lane) - 1));
    int leader = __ffs(mask) - 1;
    if (lane == leader) wcnt[w][key] = __popc(mask);
    __syncthreads();

    int rank = lrank;
#pragma unroll
    for (int ww = 0; ww < 4; ww++)
        if (ww < w) rank += wcnt[ww][key];
    int pos = g_counts[(b * T + key) * NCH + ch] + rank;
    g_sortidx[b * N + pos] = token;
}

// ---------------- K4: grouped attention via warp MMA -------------------------
// QK: bf16 3-term split. PV: P fp16 hi/lo x V single fp16 (2 MMAs).
// Q,K smem rows padded to 40 bf16 (80 B): ldmatrix conflict-free.
// V transposed Vt[dim][key] fp16, rows 136 halves (272 B) -> conflict-free.
#define ATP 40
#define VTP 136
#define SQH 0
#define SQL (SQH + GS * ATP * 2)          // 10240 each
#define SKH (SQL + GS * ATP * 2)
#define SKL (SKH + GS * ATP * 2)
#define SVH (SKL + GS * ATP * 2)          // Vt fp16: 32*272 = 8704
#define STOK (SVH + D * VTP * 2)
#define SM_ATTN (STOK + GS * 4)           // 50,176 B

__global__ void __launch_bounds__(256, 2)
k_attn_mma(const float* __restrict__ qkv, const float* __restrict__ logit_scale) {
    extern __shared__ char sm[];
    uint32_t sb = smem_u32(sm);
    int head = blockIdx.x, g = blockIdx.y, b = blockIdx.z;
    int tid = threadIdx.x;
    int* toks = (int*)(sm + STOK);

    int r = tid >> 1, h = tid & 1;           // 2 threads per token row
    int token = g_sortidx[b * N + g * GS + r];
    if (h == 0) toks[r] = token;

    float scale = __expf(fminf(logit_scale[0], 4.6051701859880914f));  // log(100)

    // ---- gather: split q (pre-scaled), k into smem; v transposed fp16 ----
    const float4* base =
        (const float4*)(qkv + ((size_t)(b * N) + token) * C3 + head * D);
#pragma unroll
    for (int p = h * 4; p < h * 4 + 4; p += 2) {   // q: 2 float4 pairs
        float4 v0 = base[p], v1 = base[p + 1];
        v0.x *= scale; v0.y *= scale; v0.z *= scale; v0.w *= scale;
        v1.x *= scale; v1.y *= scale; v1.z *= scale; v1.w *= scale;
        uint32_t h0, l0, h1, l1, h2, l2, h3, l3;
        split2(v0.x, v0.y, h0, l0); split2(v0.z, v0.w, h1, l1);
        split2(v1.x, v1.y, h2, l2); split2(v1.z, v1.w, h3, l3);
        *(uint2*)(sm + SQH + r * (ATP * 2) + p * 8)     = make_uint2(h0, h1);
        *(uint2*)(sm + SQH + r * (ATP * 2) + p * 8 + 8) = make_uint2(h2, h3);
        *(uint2*)(sm + SQL + r * (ATP * 2) + p * 8)     = make_uint2(l0, l1);
        *(uint2*)(sm + SQL + r * (ATP * 2) + p * 8 + 8) = make_uint2(l2, l3);
    }
#pragma unroll
    for (int p = h * 4; p < h * 4 + 4; p += 2) {   // k (+256 floats = +64 float4)
        float4 v0 = base[64 + p], v1 = base[64 + p + 1];
        uint32_t h0, l0, h1, l1, h2, l2, h3, l3;
        split2(v0.x, v0.y, h0, l0); split2(v0.z, v0.w, h1, l1);
        split2(v1.x, v1.y, h2, l2); split2(v1.z, v1.w, h3, l3);
        *(uint2*)(sm + SKH + r * (ATP * 2) + p * 8)     = make_uint2(h0, h1);
        *(uint2*)(sm + SKH + r * (ATP * 2) + p * 8 + 8) = make_uint2(h2, h3);
        *(uint2*)(sm + SKL + r * (ATP * 2) + p * 8)     = make_uint2(l0, l1);
        *(uint2*)(sm + SKL + r * (ATP * 2) + p * 8 + 8) = make_uint2(l2, l3);
    }
    {
        __half* vh = (__half*)(sm + SVH);
#pragma unroll
        for (int p = h * 4; p < h * 4 + 4; p++) {  // v (+512 floats = +128 float4)
            float4 v = base[128 + p];
            __half2 H0 = __floats2half2_rn(v.x, v.y);
            __half2 H1 = __floats2half2_rn(v.z, v.w);
            int d0 = p * 4;
            vh[(d0 + 0) * VTP + r] = H0.x;
            vh[(d0 + 1) * VTP + r] = H0.y;
            vh[(d0 + 2) * VTP + r] = H1.x;
            vh[(d0 + 3) * VTP + r] = H1.y;
        }
    }
    __syncthreads();

    int w = tid >> 5, lane = tid & 31;
    int gq = lane >> 2, t = lane & 3;
    int quad = lane >> 3, rrow = lane & 7;   // ldmatrix lane decomposition

    // ---- Q fragments via ldmatrix.x4 (A-operand, 16 rows x k16 per ki) ----
    uint32_t qh[2][4], ql[2][4];
    {
        int qrow = w * 16 + (quad & 1) * 8 + rrow;
#pragma unroll
        for (int ki = 0; ki < 2; ki++) {
            uint32_t off = qrow * 80 + ki * 32 + (quad >> 1) * 16;
            ldsm4(qh[ki], sb + SQH + off);
            ldsm4(ql[ki], sb + SQL + off);
        }
    }

    // ---- S = (scale*Q) K^T, 16x128 per warp in registers ----
    float S[16][4];
#pragma unroll
    for (int ni = 0; ni < 16; ni++)
#pragma unroll
        for (int rr = 0; rr < 4; rr++) S[ni][rr] = 0.f;

#pragma unroll
    for (int np = 0; np < 8; np++) {         // pairs of 8-key B tiles
        int krow = np * 16 + (quad >> 1) * 8 + rrow;
#pragma unroll
        for (int ki = 0; ki < 2; ki++) {
            uint32_t off = krow * 80 + ki * 32 + (quad & 1) * 16;
            uint32_t bh[4], bl[4];
            ldsm4(bh, sb + SKH + off);       // {b0,b1}=ni_even, {b2,b3}=ni_odd
            ldsm4(bl, sb + SKL + off);
            mma16816(S[2 * np],     qh[ki], bh);
            mma16816(S[2 * np],     qh[ki], bl);
            mma16816(S[2 * np],     ql[ki], bh);
            mma16816(S[2 * np + 1], qh[ki], bh + 2);
            mma16816(S[2 * np + 1], qh[ki], bl + 2);
            mma16816(S[2 * np + 1], ql[ki], bh + 2);
        }
    }

    // ---- softmax (two-pass, quad-shuffle row reductions) ----
    float mx0 = -INFINITY, mx1 = -INFINITY;
#pragma unroll
    for (int ni = 0; ni < 16; ni++) {
        mx0 = fmaxf(mx0, fmaxf(S[ni][0], S[ni][1]));
        mx1 = fmaxf(mx1, fmaxf(S[ni][2], S[ni][3]));
    }
#pragma unroll
    for (int x = 1; x <= 2; x <<= 1) {
        mx0 = fmaxf(mx0, __shfl_xor_sync(0xffffffffu, mx0, x));
        mx1 = fmaxf(mx1, __shfl_xor_sync(0xffffffffu, mx1, x));
    }

    float sm0 = 0.f, sm1 = 0.f;
#pragma unroll
    for (int ni = 0; ni < 16; ni++) {
        S[ni][0] = __expf(S[ni][0] - mx0);
        S[ni][1] = __expf(S[ni][1] - mx0);
        S[ni][2] = __expf(S[ni][2] - mx1);
        S[ni][3] = __expf(S[ni][3] - mx1);
        sm0 += S[ni][0] + S[ni][1];
        sm1 += S[ni][2] + S[ni][3];
    }
#pragma unroll
    for (int x = 1; x <= 2; x <<= 1) {
        sm0 += __shfl_xor_sync(0xffffffffu, sm0, x);
        sm1 += __shfl_xor_sync(0xffffffffu, sm1, x);
    }

    // ---- Y = P V  (P fp16 hi/lo from S registers, V single fp16) ----
    float Y[4][4];
#pragma unroll
    for (int nj = 0; nj < 4; nj++)
#pragma unroll
        for (int rr = 0; rr < 4; rr++) Y[nj][rr] = 0.f;

#pragma unroll
    for (int kk = 0; kk < 8; kk++) {
        uint32_t ph[4], pl[4];
        split2h(S[2 * kk][0],     S[2 * kk][1],     ph[0], pl[0]);
        split2h(S[2 * kk][2],     S[2 * kk][3],     ph[1], pl[1]);
        split2h(S[2 * kk + 1][0], S[2 * kk + 1][1], ph[2], pl[2]);
        split2h(S[2 * kk + 1][2], S[2 * kk + 1][3], ph[3], pl[3]);
#pragma unroll
        for (int njp = 0; njp < 2; njp++) {
            int vrow = njp * 16 + (quad >> 1) * 8 + rrow;
            uint32_t off = vrow * 272 + kk * 32 + (quad & 1) * 16;
            uint32_t bv[4];
            ldsm4(bv, sb + SVH + off);       // {b0,b1}=nj_even, {b2,b3}=nj_odd
            mma16816h(Y[2 * njp],     ph, bv);
            mma16816h(Y[2 * njp],     pl, bv);
            mma16816h(Y[2 * njp + 1], ph, bv + 2);
            mma16816h(Y[2 * njp + 1], pl, bv + 2);
        }
    }

    // ---- epilogue: normalize, fp16 hi/lo split, scatter to ORIGINAL order ----
    float i0 = 1.0f / sm0, i1 = 1.0f / sm1;
    int row0 = w * 16 + gq;
    size_t off0 = ((size_t)(b * N) + toks[row0]) * C + head * D;
    size_t off1 = ((size_t)(b * N) + toks[row0 + 8]) * C + head * D;
#pragma unroll
    for (int nj = 0; nj < 4; nj++) {
        uint32_t hh, ll;
        split2h(Y[nj][0] * i0, Y[nj][1] * i0, hh, ll);
        *(uint32_t*)(g_yh + off0 + nj * 8 + 2 * t) = hh;
        *(uint32_t*)(g_yl + off0 + nj * 8 + 2 * t) = ll;
        split2h(Y[nj][2] * i1, Y[nj][3] * i1, hh, ll);
        *(uint32_t*)(g_yh + off1 + nj * 8 + 2 * t) = hh;
        *(uint32_t*)(g_yl + off1 + nj * 8 + 2 * t) = ll;
    }
}

// ---------------- K5: projection GEMM (y fp16 hi/lo x W single fp16) ---------
// Block 128(M) x 64(N), 8 warps (4m x 2n), warp tile 32x32, 2 MMAs per tile.
// Double-buffered cp.async pipeline.
#define PM 128
#define PN 64
#define PKC 64
#define PSTR 72                 // fp16 elements per smem row (144 B)
#define SA_HI 0
#define SA_LO (PM * PSTR * 2)
#define SB_W  (SA_LO + PM * PSTR * 2)
#define SM_BUF (SB_W + PN * PSTR * 2)     // 46080 B per buffer
#define SM_PROJ (2 * SM_BUF)              // 92160 B

__global__ void __launch_bounds__(256)
k_proj_mma(const float* __restrict__ bias, float* __restrict__ out) {
    extern __shared__ char sm[];
    uint32_t sb = smem_u32(sm);
    int tid = threadIdx.x;
    int wid = tid >> 5, lane = tid & 31;
    int g = lane >> 2, t = lane & 3;
    int wm = wid >> 1, wn = wid & 1;          // 4 x 2 warp grid
    int m0 = blockIdx.y * PM, n0 = blockIdx.x * PN;
    const int RS = PSTR / 2;                  // 36 words per row

    // async fill of one chunk into buffer at byte offset `boff`
    auto fill = [&](int ch, uint32_t boff) {
        uint32_t bA = sb + boff;
#pragma unroll
        for (int i = tid; i < PM * (PKC / 8); i += 256) {   // 1024 segs, 4 iters
            int r = i >> 3, s = i & 7;
            size_t src = (size_t)(m0 + r) * C + ch * PKC + s * 8;
            uint32_t off = (uint32_t)(r * (PSTR * 2) + s * 16);
            cp16(bA + SA_HI + off, g_yh + src);
            cp16(bA + SA_LO + off, g_yl + src);
        }
#pragma unroll
        for (int i = tid; i < PN * (PKC / 8); i += 256) {   // 512 segs, 2 iters
            int r = i >> 3, s = i & 7;
            size_t src = (size_t)(n0 + r) * C + ch * PKC + s * 8;
            uint32_t off = (uint32_t)(r * (PSTR * 2) + s * 16);
            cp16(bA + SB_W + off, g_wf + src);
        }
        asm volatile("cp.async.commit_group;" ::: "memory");
    };

    float acc[2][4][4];
#pragma unroll
    for (int mi = 0; mi < 2; mi++)
#pragma unroll
        for (int ni = 0; ni < 4; ni++)
#pragma unroll
            for (int r = 0; r < 4; r++) acc[mi][ni][r] = 0.f;

    fill(0, 0);
    int cur = 0;

#pragma unroll
    for (int ch = 0; ch < C / PKC; ch++) {
        if (ch < C / PKC - 1) {
            fill(ch + 1, (uint32_t)((cur ^ 1) * SM_BUF));
            asm volatile("cp.async.wait_group 1;" ::: "memory");
        } else {
            asm volatile("cp.async.wait_group 0;" ::: "memory");
        }
        __syncthreads();

        const char* bufc = sm + cur * SM_BUF;
        const uint32_t* Ah = (const uint32_t*)(bufc + SA_HI);
        const uint32_t* Al = (const uint32_t*)(bufc + SA_LO);
        const uint32_t* Bw = (const uint32_t*)(bufc + SB_W);

#pragma unroll
        for (int ksi = 0; ksi < PKC / 16; ksi++) {
            int kw = ksi * 8 + t;

            uint32_t ah[2][4], al[2][4];
#pragma unroll
            for (int mi = 0; mi < 2; mi++) {
                int rb = (wm * 32 + mi * 16 + g) * RS + kw;
                ah[mi][0] = Ah[rb];              al[mi][0] = Al[rb];
                ah[mi][1] = Ah[rb + 8 * RS];     al[mi][1] = Al[rb + 8 * RS];
                ah[mi][2] = Ah[rb + 4];          al[mi][2] = Al[rb + 4];
                ah[mi][3] = Ah[rb + 8 * RS + 4]; al[mi][3] = Al[rb + 8 * RS + 4];
            }
            uint32_t bf[4][2];
#pragma unroll
            for (int ni = 0; ni < 4; ni++) {
                int rb = (wn * 32 + ni * 8 + g) * RS + kw;
                bf[ni][0] = Bw[rb];
                bf[ni][1] = Bw[rb + 4];
            }
#pragma unroll
            for (int mi = 0; mi < 2; mi++)
#pragma unroll
                for (int ni = 0; ni < 4; ni++) {
                    mma16816h(acc[mi][ni], ah[mi], bf[ni]);   // hi term
                    mma16816h(acc[mi][ni], al[mi], bf[ni]);   // lo term
                }
        }
        __syncthreads();   // MMA reads done before this buffer is refilled
        cur ^= 1;
    }

#pragma unroll
    for (int ni = 0; ni < 4; ni++) {
        int cn = n0 + wn * 32 + ni * 8 + t * 2;
        float2 bb = *(const float2*)(bias + cn);
#pragma unroll
        for (int mi = 0; mi < 2; mi++) {
            int r0 = m0 + wm * 32 + mi * 16 + g;
            float2 o0, o1;
            o0.x = acc[mi][ni][0] + bb.x;
            o0.y = acc[mi][ni][1] + bb.y;
            o1.x = acc[mi][ni][2] + bb.x;
            o1.y = acc[mi][ni][3] + bb.y;
            *(float2*)(out + (size_t)r0 * C + cn)       = o0;
            *(float2*)(out + (size_t)(r0 + 8) * C + cn) = o1;
        }
    }
}

// ---------------- launch ----------------
extern "C" void kernel_launch(void* const* d_in, const int* in_sizes, int n_in,
                              void* d_out, int out_size) {
    const float* qkv  = (const float*)d_in[0];
    const float* sim  = (const float*)d_in[1];
    const float* W    = (const float*)d_in[2];
    const float* bias = (const float*)d_in[3];
    const float* ls   = (const float*)d_in[4];
    float* out = (float*)d_out;

    cudaFuncSetAttribute(k_attn_mma, cudaFuncAttributeMaxDynamicSharedMemorySize,
                         SM_ATTN);
    cudaFuncSetAttribute(k_proj_mma, cudaFuncAttributeMaxDynamicSharedMemorySize,
                         SM_PROJ);

    k_argmax_count<<<dim3(NCH, B), CHUNK>>>(sim);
    k_scan<<<B, 1024>>>(W);
    k_scatter<<<dim3(NCH, B), CHUNK>>>();
    k_attn_mma<<<dim3(HDS, NG, B), 256, SM_ATTN>>>(qkv, ls);
    k_proj_mma<<<dim3(C / PN, (B * N) / PM), 256, SM_PROJ>>>(bias, out);
}

// round 14
// speedup vs baseline: 1.3025x; 1.0096x over previous
#include <cuda_runtime.h>
#include <cuda_bf16.h>
#include <cuda_fp16.h>
#include <math.h>
#include <cstdint>

// Problem constants (fixed by the dataset)
#define B    4
#define N    16384
#define C    256
#define C3   768
#define T    64        // categories
#define HDS  8
#define D    32        // head dim
#define GS   128       // group size
#define NG   128       // groups per batch
#define CHUNK 128
#define NCH   128      // N / CHUNK

// ---------------- scratch (static device allocations only) ----------------
__device__ int   g_tkid[B * N];
__device__ int   g_counts[B * T * NCH];     // [b][key][chunk], scanned in place
__device__ int   g_sortidx[B * N];          // sorted position -> original token
// attention output in ORIGINAL token order, fp16 hi/lo (exact to 2^-22)
__device__ __half g_yh[(size_t)B * N * C];
__device__ __half g_yl[(size_t)B * N * C];
// projection weight, single fp16 (2^-12 rounding)
__device__ __half g_wf[C * C];

// bf16 hi/lo split of a pair of floats, packed as bf16x2 words
__device__ __forceinline__ void split2(float a, float b, uint32_t& hi, uint32_t& lo) {
    __nv_bfloat162 h = __floats2bfloat162_rn(a, b);
    float ra = a - __bfloat162float(h.x);
    float rb = b - __bfloat162float(h.y);
    __nv_bfloat162 l = __floats2bfloat162_rn(ra, rb);
    hi = *(uint32_t*)&h;
    lo = *(uint32_t*)&l;
}
// fp16 hi/lo split (residual exact to ~2^-22)
__device__ __forceinline__ void split2h(float a, float b, uint32_t& hi, uint32_t& lo) {
    __half2 h = __floats2half2_rn(a, b);
    float ra = a - __low2float(h);
    float rb = b - __high2float(h);
    __half2 l = __floats2half2_rn(ra, rb);
    hi = *(uint32_t*)&h;
    lo = *(uint32_t*)&l;
}

// warp-level bf16 MMA, fp32 accumulate
__device__ __forceinline__ void mma16816(float* c, const uint32_t* a, const uint32_t* b) {
    asm volatile(
        "mma.sync.aligned.m16n8k16.row.col.f32.bf16.bf16.f32 "
        "{%0,%1,%2,%3}, {%4,%5,%6,%7}, {%8,%9}, {%0,%1,%2,%3};"
        : "+f"(c[0]), "+f"(c[1]), "+f"(c[2]), "+f"(c[3])
        : "r"(a[0]), "r"(a[1]), "r"(a[2]), "r"(a[3]), "r"(b[0]), "r"(b[1]));
}
// warp-level fp16 MMA, fp32 accumulate
__device__ __forceinline__ void mma16816h(float* c, const uint32_t* a, const uint32_t* b) {
    asm volatile(
        "mma.sync.aligned.m16n8k16.row.col.f32.f16.f16.f32 "
        "{%0,%1,%2,%3}, {%4,%5,%6,%7}, {%8,%9}, {%0,%1,%2,%3};"
        : "+f"(c[0]), "+f"(c[1]), "+f"(c[2]), "+f"(c[3])
        : "r"(a[0]), "r"(a[1]), "r"(a[2]), "r"(a[3]), "r"(b[0]), "r"(b[1]));
}

__device__ __forceinline__ uint32_t smem_u32(const void* p) {
    uint32_t a;
    asm("{ .reg .u64 t; cvta.to.shared.u64 t, %1; cvt.u32.u64 %0, t; }"
        : "=r"(a) : "l"(p));
    return a;
}
__device__ __forceinline__ void ldsm4(uint32_t* r, uint32_t addr) {
    asm volatile("ldmatrix.sync.aligned.m8n8.x4.shared.b16 {%0,%1,%2,%3}, [%4];"
                 : "=r"(r[0]), "=r"(r[1]), "=r"(r[2]), "=r"(r[3]) : "r"(addr));
}
__device__ __forceinline__ void cp16(uint32_t dst, const void* src) {
    asm volatile("cp.async.cg.shared.global [%0], [%1], 16;"
                 :: "r"(dst), "l"(src) : "memory");
}

// ---------------- K1: per-token argmax + per-chunk histogram ----------------
// Staging rows padded to T+1=65 floats -> conflict-free reads.
__global__ void k_argmax_count(const float* __restrict__ sim) {
    int b = blockIdx.y, ch = blockIdx.x, tid = threadIdx.x;
    __shared__ float ss[CHUNK * (T + 1)];   // 33.3 KB
    __shared__ int   hist[T];

    const float4* src = (const float4*)(sim + ((size_t)(b * N + ch * CHUNK)) * T);
#pragma unroll
    for (int i = tid; i < CHUNK * T / 4; i += CHUNK) {
        float4 v = src[i];
        int row = i >> 4, c = (i & 15) * 4;
        float* d = ss + row * (T + 1) + c;
        d[0] = v.x; d[1] = v.y; d[2] = v.z; d[3] = v.w;
    }
    if (tid < T) hist[tid] = 0;
    __syncthreads();

    const float* row = ss + tid * (T + 1);
    float best = row[0];
    int   bi   = 0;
#pragma unroll
    for (int j = 1; j < T; j++) {
        float v = row[j];
        if (v > best) { best = v; bi = j; }   // first-max == jnp.argmax tie rule
    }
    g_tkid[b * N + ch * CHUNK + tid] = bi;
    atomicAdd(&hist[bi], 1);
    __syncthreads();
    if (tid < T) g_counts[(b * T + tid) * NCH + ch] = hist[tid];
}

// ---------------- K2: per-batch exclusive scan of counts + W fp16 convert ----
__global__ void k_scan(const float* __restrict__ W) {
    const int PER = (T * NCH) / 1024;   // 8
    int b = blockIdx.x, tid = threadIdx.x;
    __shared__ int t1[1024], t2[1024];
    int* cnt = g_counts + b * T * NCH;

    // fold in W->fp16 conversion (4 blocks x 1024 thr x 4 float4 = 16384)
#pragma unroll
    for (int j = 0; j < 4; j++) {
        int i = (b * 1024 + tid) * 4 + j;
        float4 v = ((const float4*)W)[i];
        __half2 a = __floats2half2_rn(v.x, v.y);
        __half2 c = __floats2half2_rn(v.z, v.w);
        uint2 o;
        o.x = *(uint32_t*)&a;
        o.y = *(uint32_t*)&c;
        *(uint2*)(g_wf + i * 4) = o;
    }

    int v[PER];
    int s = 0;
#pragma unroll
    for (int i = 0; i < PER; i++) { v[i] = cnt[tid * PER + i]; s += v[i]; }
    t1[tid] = s;
    __syncthreads();

    int* a  = t1;
    int* bb = t2;
    for (int off = 1; off < 1024; off <<= 1) {
        int x = a[tid];
        if (tid >= off) x += a[tid - off];
        bb[tid] = x;
        __syncthreads();
        int* tmp = a; a = bb; bb = tmp;
    }
    int pre = (tid == 0) ? 0 : a[tid - 1];
#pragma unroll
    for (int i = 0; i < PER; i++) { cnt[tid * PER + i] = pre; pre += v[i]; }
}

// ---------------- K3: stable scatter (match_any rank, no serial loop) --------
__global__ void k_scatter() {
    int b = blockIdx.y, ch = blockIdx.x, tid = threadIdx.x;
    __shared__ int wcnt[4][T];
    int w = tid >> 5, lane = tid & 31;
    for (int i = tid; i < 4 * T; i += CHUNK) ((int*)wcnt)[i] = 0;
    __syncthreads();

    int token = ch * CHUNK + tid;
    int key   = g_tkid[b * N + token];
    unsigned mask  = __match_any_sync(0xffffffffu, key);
    int lrank  = __popc(mask & ((1u << lane) - 1));
    int leader = __ffs(mask) - 1;
    if (lane == leader) wcnt[w][key] = __popc(mask);
    __syncthreads();

    int rank = lrank;
#pragma unroll
    for (int ww = 0; ww < 4; ww++)
        if (ww < w) rank += wcnt[ww][key];
    int pos = g_counts[(b * T + key) * NCH + ch] + rank;
    g_sortidx[b * N + pos] = token;
}

// ---------------- K4: grouped attention via warp MMA -------------------------
// QK: bf16 3-term split. PV: P fp16 hi/lo x V single fp16 (2 MMAs).
#define ATP 40
#define VTP 136
#define SQH 0
#define SQL (SQH + GS * ATP * 2)          // 10240 each
#define SKH (SQL + GS * ATP * 2)
#define SKL (SKH + GS * ATP * 2)
#define SVH (SKL + GS * ATP * 2)          // Vt fp16: 32*272 = 8704
#define STOK (SVH + D * VTP * 2)
#define SM_ATTN (STOK + GS * 4)           // 50,176 B

__global__ void __launch_bounds__(256, 2)
k_attn_mma(const float* __restrict__ qkv, const float* __restrict__ logit_scale) {
    extern __shared__ char sm[];
    uint32_t sb = smem_u32(sm);
    int head = blockIdx.x, g = blockIdx.y, b = blockIdx.z;
    int tid = threadIdx.x;
    int* toks = (int*)(sm + STOK);

    int r = tid >> 1, h = tid & 1;           // 2 threads per token row
    int token = g_sortidx[b * N + g * GS + r];
    if (h == 0) toks[r] = token;

    float scale = __expf(fminf(logit_scale[0], 4.6051701859880914f));  // log(100)

    // ---- gather: split q (pre-scaled), k into smem; v transposed fp16 ----
    const float4* base =
        (const float4*)(qkv + ((size_t)(b * N) + token) * C3 + head * D);
#pragma unroll
    for (int p = h * 4; p < h * 4 + 4; p += 2) {   // q: 2 float4 pairs
        float4 v0 = base[p], v1 = base[p + 1];
        v0.x *= scale; v0.y *= scale; v0.z *= scale; v0.w *= scale;
        v1.x *= scale; v1.y *= scale; v1.z *= scale; v1.w *= scale;
        uint32_t h0, l0, h1, l1, h2, l2, h3, l3;
        split2(v0.x, v0.y, h0, l0); split2(v0.z, v0.w, h1, l1);
        split2(v1.x, v1.y, h2, l2); split2(v1.z, v1.w, h3, l3);
        *(uint2*)(sm + SQH + r * (ATP * 2) + p * 8)     = make_uint2(h0, h1);
        *(uint2*)(sm + SQH + r * (ATP * 2) + p * 8 + 8) = make_uint2(h2, h3);
        *(uint2*)(sm + SQL + r * (ATP * 2) + p * 8)     = make_uint2(l0, l1);
        *(uint2*)(sm + SQL + r * (ATP * 2) + p * 8 + 8) = make_uint2(l2, l3);
    }
#pragma unroll
    for (int p = h * 4; p < h * 4 + 4; p += 2) {   // k (+256 floats = +64 float4)
        float4 v0 = base[64 + p], v1 = base[64 + p + 1];
        uint32_t h0, l0, h1, l1, h2, l2, h3, l3;
        split2(v0.x, v0.y, h0, l0); split2(v0.z, v0.w, h1, l1);
        split2(v1.x, v1.y, h2, l2); split2(v1.z, v1.w, h3, l3);
        *(uint2*)(sm + SKH + r * (ATP * 2) + p * 8)     = make_uint2(h0, h1);
        *(uint2*)(sm + SKH + r * (ATP * 2) + p * 8 + 8) = make_uint2(h2, h3);
        *(uint2*)(sm + SKL + r * (ATP * 2) + p * 8)     = make_uint2(l0, l1);
        *(uint2*)(sm + SKL + r * (ATP * 2) + p * 8 + 8) = make_uint2(l2, l3);
    }
    {
        __half* vh = (__half*)(sm + SVH);
#pragma unroll
        for (int p = h * 4; p < h * 4 + 4; p++) {  // v (+512 floats = +128 float4)
            float4 v = base[128 + p];
            __half2 H0 = __floats2half2_rn(v.x, v.y);
            __half2 H1 = __floats2half2_rn(v.z, v.w);
            int d0 = p * 4;
            vh[(d0 + 0) * VTP + r] = H0.x;
            vh[(d0 + 1) * VTP + r] = H0.y;
            vh[(d0 + 2) * VTP + r] = H1.x;
            vh[(d0 + 3) * VTP + r] = H1.y;
        }
    }
    __syncthreads();

    int w = tid >> 5, lane = tid & 31;
    int gq = lane >> 2, t = lane & 3;
    int quad = lane >> 3, rrow = lane & 7;   // ldmatrix lane decomposition

    // ---- Q fragments via ldmatrix.x4 (A-operand, 16 rows x k16 per ki) ----
    uint32_t qh[2][4], ql[2][4];
    {
        int qrow = w * 16 + (quad & 1) * 8 + rrow;
#pragma unroll
        for (int ki = 0; ki < 2; ki++) {
            uint32_t off = qrow * 80 + ki * 32 + (quad >> 1) * 16;
            ldsm4(qh[ki], sb + SQH + off);
            ldsm4(ql[ki], sb + SQL + off);
        }
    }

    // ---- S = (scale*Q) K^T, 16x128 per warp in registers ----
    float S[16][4];
#pragma unroll
    for (int ni = 0; ni < 16; ni++)
#pragma unroll
        for (int rr = 0; rr < 4; rr++) S[ni][rr] = 0.f;

#pragma unroll
    for (int np = 0; np < 8; np++) {         // pairs of 8-key B tiles
        int krow = np * 16 + (quad >> 1) * 8 + rrow;
#pragma unroll
        for (int ki = 0; ki < 2; ki++) {
            uint32_t off = krow * 80 + ki * 32 + (quad & 1) * 16;
            uint32_t bh[4], bl[4];
            ldsm4(bh, sb + SKH + off);       // {b0,b1}=ni_even, {b2,b3}=ni_odd
            ldsm4(bl, sb + SKL + off);
            mma16816(S[2 * np],     qh[ki], bh);
            mma16816(S[2 * np],     qh[ki], bl);
            mma16816(S[2 * np],     ql[ki], bh);
            mma16816(S[2 * np + 1], qh[ki], bh + 2);
            mma16816(S[2 * np + 1], qh[ki], bl + 2);
            mma16816(S[2 * np + 1], ql[ki], bh + 2);
        }
    }

    // ---- softmax (two-pass, quad-shuffle row reductions) ----
    float mx0 = -INFINITY, mx1 = -INFINITY;
#pragma unroll
    for (int ni = 0; ni < 16; ni++) {
        mx0 = fmaxf(mx0, fmaxf(S[ni][0], S[ni][1]));
        mx1 = fmaxf(mx1, fmaxf(S[ni][2], S[ni][3]));
    }
#pragma unroll
    for (int x = 1; x <= 2; x <<= 1) {
        mx0 = fmaxf(mx0, __shfl_xor_sync(0xffffffffu, mx0, x));
        mx1 = fmaxf(mx1, __shfl_xor_sync(0xffffffffu, mx1, x));
    }

    float sm0 = 0.f, sm1 = 0.f;
#pragma unroll
    for (int ni = 0; ni < 16; ni++) {
        S[ni][0] = __expf(S[ni][0] - mx0);
        S[ni][1] = __expf(S[ni][1] - mx0);
        S[ni][2] = __expf(S[ni][2] - mx1);
        S[ni][3] = __expf(S[ni][3] - mx1);
        sm0 += S[ni][0] + S[ni][1];
        sm1 += S[ni][2] + S[ni][3];
    }
#pragma unroll
    for (int x = 1; x <= 2; x <<= 1) {
        sm0 += __shfl_xor_sync(0xffffffffu, sm0, x);
        sm1 += __shfl_xor_sync(0xffffffffu, sm1, x);
    }

    // ---- Y = P V  (P fp16 hi/lo from S registers, V single fp16) ----
    float Y[4][4];
#pragma unroll
    for (int nj = 0; nj < 4; nj++)
#pragma unroll
        for (int rr = 0; rr < 4; rr++) Y[nj][rr] = 0.f;

#pragma unroll
    for (int kk = 0; kk < 8; kk++) {
        uint32_t ph[4], pl[4];
        split2h(S[2 * kk][0],     S[2 * kk][1],     ph[0], pl[0]);
        split2h(S[2 * kk][2],     S[2 * kk][3],     ph[1], pl[1]);
        split2h(S[2 * kk + 1][0], S[2 * kk + 1][1], ph[2], pl[2]);
        split2h(S[2 * kk + 1][2], S[2 * kk + 1][3], ph[3], pl[3]);
#pragma unroll
        for (int njp = 0; njp < 2; njp++) {
            int vrow = njp * 16 + (quad >> 1) * 8 + rrow;
            uint32_t off = vrow * 272 + kk * 32 + (quad & 1) * 16;
            uint32_t bv[4];
            ldsm4(bv, sb + SVH + off);       // {b0,b1}=nj_even, {b2,b3}=nj_odd
            mma16816h(Y[2 * njp],     ph, bv);
            mma16816h(Y[2 * njp],     pl, bv);
            mma16816h(Y[2 * njp + 1], ph, bv + 2);
            mma16816h(Y[2 * njp + 1], pl, bv + 2);
        }
    }

    // ---- epilogue: normalize, fp16 hi/lo split, scatter to ORIGINAL order ----
    float i0 = 1.0f / sm0, i1 = 1.0f / sm1;
    int row0 = w * 16 + gq;
    size_t off0 = ((size_t)(b * N) + toks[row0]) * C + head * D;
    size_t off1 = ((size_t)(b * N) + toks[row0 + 8]) * C + head * D;
#pragma unroll
    for (int nj = 0; nj < 4; nj++) {
        uint32_t hh, ll;
        split2h(Y[nj][0] * i0, Y[nj][1] * i0, hh, ll);
        *(uint32_t*)(g_yh + off0 + nj * 8 + 2 * t) = hh;
        *(uint32_t*)(g_yl + off0 + nj * 8 + 2 * t) = ll;
        split2h(Y[nj][2] * i1, Y[nj][3] * i1, hh, ll);
        *(uint32_t*)(g_yh + off1 + nj * 8 + 2 * t) = hh;
        *(uint32_t*)(g_yl + off1 + nj * 8 + 2 * t) = ll;
    }
}

// ---------------- K5: projection GEMM (y fp16 hi/lo x W single fp16) ---------
// Block 128(M) x 64(N), 8 warps (4m x 2n), warp tile 32x32, 2 MMAs per tile.
// Double-buffered cp.async pipeline; fragment loads via ldmatrix.x4
// (A pattern = attn Q, B pattern = attn K; 144-B rows, banks 4r mod 32 ✓).
#define PM 128
#define PN 64
#define PKC 64
#define PSTR 72                 // fp16 elements per smem row (144 B)
#define SA_HI 0
#define SA_LO (PM * PSTR * 2)
#define SB_W  (SA_LO + PM * PSTR * 2)
#define SM_BUF (SB_W + PN * PSTR * 2)     // 46080 B per buffer
#define SM_PROJ (2 * SM_BUF)              // 92160 B

__global__ void __launch_bounds__(256)
k_proj_mma(const float* __restrict__ bias, float* __restrict__ out) {
    extern __shared__ char sm[];
    uint32_t sb = smem_u32(sm);
    int tid = threadIdx.x;
    int wid = tid >> 5, lane = tid & 31;
    int g = lane >> 2, t = lane & 3;
    int quad = lane >> 3, rrow = lane & 7;   // ldmatrix lane decomposition
    int wm = wid >> 1, wn = wid & 1;          // 4 x 2 warp grid
    int m0 = blockIdx.y * PM, n0 = blockIdx.x * PN;

    // async fill of one chunk into buffer at byte offset `boff`
    auto fill = [&](int ch, uint32_t boff) {
        uint32_t bA = sb + boff;
#pragma unroll
        for (int i = tid; i < PM * (PKC / 8); i += 256) {   // 1024 segs, 4 iters
            int r = i >> 3, s = i & 7;
            size_t src = (size_t)(m0 + r) * C + ch * PKC + s * 8;
            uint32_t off = (uint32_t)(r * (PSTR * 2) + s * 16);
            cp16(bA + SA_HI + off, g_yh + src);
            cp16(bA + SA_LO + off, g_yl + src);
        }
#pragma unroll
        for (int i = tid; i < PN * (PKC / 8); i += 256) {   // 512 segs, 2 iters
            int r = i >> 3, s = i & 7;
            size_t src = (size_t)(n0 + r) * C + ch * PKC + s * 8;
            uint32_t off = (uint32_t)(r * (PSTR * 2) + s * 16);
            cp16(bA + SB_W + off, g_wf + src);
        }
        asm volatile("cp.async.commit_group;" ::: "memory");
    };

    float acc[2][4][4];
#pragma unroll
    for (int mi = 0; mi < 2; mi++)
#pragma unroll
        for (int ni = 0; ni < 4; ni++)
#pragma unroll
            for (int r = 0; r < 4; r++) acc[mi][ni][r] = 0.f;

    fill(0, 0);
    int cur = 0;

#pragma unroll
    for (int ch = 0; ch < C / PKC; ch++) {
        if (ch < C / PKC - 1) {
            fill(ch + 1, (uint32_t)((cur ^ 1) * SM_BUF));
            asm volatile("cp.async.wait_group 1;" ::: "memory");
        } else {
            asm volatile("cp.async.wait_group 0;" ::: "memory");
        }
        __syncthreads();

        uint32_t bufb = sb + cur * SM_BUF;

#pragma unroll
        for (int ksi = 0; ksi < PKC / 16; ksi++) {
            // A fragments via ldmatrix (16 rows x 16 k-cols per mi)
            uint32_t ah[2][4], al[2][4];
#pragma unroll
            for (int mi = 0; mi < 2; mi++) {
                int arow = wm * 32 + mi * 16 + (quad & 1) * 8 + rrow;
                uint32_t off = (uint32_t)(arow * 144 + ksi * 32 + (quad >> 1) * 16);
                ldsm4(ah[mi], bufb + SA_HI + off);
                ldsm4(al[mi], bufb + SA_LO + off);
            }
            // B fragments via ldmatrix (16 n-rows -> 2 ni per ldsm4)
            uint32_t bfr[2][4];
#pragma unroll
            for (int njp = 0; njp < 2; njp++) {
                int brow = wn * 32 + njp * 16 + (quad >> 1) * 8 + rrow;
                uint32_t off = (uint32_t)(brow * 144 + ksi * 32 + (quad & 1) * 16);
                ldsm4(bfr[njp], bufb + SB_W + off);   // {0,1}=ni even, {2,3}=ni odd
            }
#pragma unroll
            for (int mi = 0; mi < 2; mi++)
#pragma unroll
                for (int ni = 0; ni < 4; ni++) {
                    const uint32_t* bp = bfr[ni >> 1] + (ni & 1) * 2;
                    mma16816h(acc[mi][ni], ah[mi], bp);   // hi term
                    mma16816h(acc[mi][ni], al[mi], bp);   // lo term
                }
        }
        __syncthreads();   // MMA reads done before this buffer is refilled
        cur ^= 1;
    }

#pragma unroll
    for (int ni = 0; ni < 4; ni++) {
        int cn = n0 + wn * 32 + ni * 8 + t * 2;
        float2 bb = *(const float2*)(bias + cn);
#pragma unroll
        for (int mi = 0; mi < 2; mi++) {
            int r0 = m0 + wm * 32 + mi * 16 + g;
            float2 o0, o1;
            o0.x = acc[mi][ni][0] + bb.x;
            o0.y = acc[mi][ni][1] + bb.y;
            o1.x = acc[mi][ni][2] + bb.x;
            o1.y = acc[mi][ni][3] + bb.y;
            *(float2*)(out + (size_t)r0 * C + cn)       = o0;
            *(float2*)(out + (size_t)(r0 + 8) * C + cn) = o1;
        }
    }
}

// ---------------- launch ----------------
extern "C" void kernel_launch(void* const* d_in, const int* in_sizes, int n_in,
                              void* d_out, int out_size) {
    const float* qkv  = (const float*)d_in[0];
    const float* sim  = (const float*)d_in[1];
    const float* W    = (const float*)d_in[2];
    const float* bias = (const float*)d_in[3];
    const float* ls   = (const float*)d_in[4];
    float* out = (float*)d_out;

    cudaFuncSetAttribute(k_attn_mma, cudaFuncAttributeMaxDynamicSharedMemorySize,
                         SM_ATTN);
    cudaFuncSetAttribute(k_proj_mma, cudaFuncAttributeMaxDynamicSharedMemorySize,
                         SM_PROJ);

    k_argmax_count<<<dim3(NCH, B), CHUNK>>>(sim);
    k_scan<<<B, 1024>>>(W);
    k_scatter<<<dim3(NCH, B), CHUNK>>>();
    k_attn_mma<<<dim3(HDS, NG, B), 256, SM_ATTN>>>(qkv, ls);
    k_proj_mma<<<dim3(C / PN, (B * N) / PM), 256, SM_PROJ>>>(bias, out);
}

// round 15
// speedup vs baseline: 1.3352x; 1.0251x over previous
#include <cuda_runtime.h>
#include <cuda_bf16.h>
#include <cuda_fp16.h>
#include <math.h>
#include <cstdint>

// Problem constants (fixed by the dataset)
#define B    4
#define N    16384
#define C    256
#define C3   768
#define T    64        // categories
#define HDS  8
#define D    32        // head dim
#define GS   128       // group size
#define NG   128       // groups per batch
#define CHUNK 128
#define NCH   128      // N / CHUNK

// ---------------- scratch (static device allocations only) ----------------
__device__ int   g_tkid[B * N];
__device__ int   g_counts[B * T * NCH];     // [b][key][chunk], scanned in place
__device__ int   g_sortidx[B * N];          // sorted position -> original token
// attention output in ORIGINAL token order, fp16 hi/lo (exact to 2^-22)
__device__ __half g_yh[(size_t)B * N * C];
__device__ __half g_yl[(size_t)B * N * C];
// projection weight, single fp16 (2^-12 rounding)
__device__ __half g_wf[C * C];

// bf16 hi/lo split of a pair of floats, packed as bf16x2 words
__device__ __forceinline__ void split2(float a, float b, uint32_t& hi, uint32_t& lo) {
    __nv_bfloat162 h = __floats2bfloat162_rn(a, b);
    float ra = a - __bfloat162float(h.x);
    float rb = b - __bfloat162float(h.y);
    __nv_bfloat162 l = __floats2bfloat162_rn(ra, rb);
    hi = *(uint32_t*)&h;
    lo = *(uint32_t*)&l;
}
// fp16 hi/lo split (residual exact to ~2^-22)
__device__ __forceinline__ void split2h(float a, float b, uint32_t& hi, uint32_t& lo) {
    __half2 h = __floats2half2_rn(a, b);
    float ra = a - __low2float(h);
    float rb = b - __high2float(h);
    __half2 l = __floats2half2_rn(ra, rb);
    hi = *(uint32_t*)&h;
    lo = *(uint32_t*)&l;
}

// warp-level bf16 MMA, fp32 accumulate
__device__ __forceinline__ void mma16816(float* c, const uint32_t* a, const uint32_t* b) {
    asm volatile(
        "mma.sync.aligned.m16n8k16.row.col.f32.bf16.bf16.f32 "
        "{%0,%1,%2,%3}, {%4,%5,%6,%7}, {%8,%9}, {%0,%1,%2,%3};"
        : "+f"(c[0]), "+f"(c[1]), "+f"(c[2]), "+f"(c[3])
        : "r"(a[0]), "r"(a[1]), "r"(a[2]), "r"(a[3]), "r"(b[0]), "r"(b[1]));
}
// warp-level fp16 MMA, fp32 accumulate
__device__ __forceinline__ void mma16816h(float* c, const uint32_t* a, const uint32_t* b) {
    asm volatile(
        "mma.sync.aligned.m16n8k16.row.col.f32.f16.f16.f32 "
        "{%0,%1,%2,%3}, {%4,%5,%6,%7}, {%8,%9}, {%0,%1,%2,%3};"
        : "+f"(c[0]), "+f"(c[1]), "+f"(c[2]), "+f"(c[3])
        : "r"(a[0]), "r"(a[1]), "r"(a[2]), "r"(a[3]), "r"(b[0]), "r"(b[1]));
}

__device__ __forceinline__ uint32_t smem_u32(const void* p) {
    uint32_t a;
    asm("{ .reg .u64 t; cvta.to.shared.u64 t, %1; cvt.u32.u64 %0, t; }"
        : "=r"(a) : "l"(p));
    return a;
}
__device__ __forceinline__ void ldsm4(uint32_t* r, uint32_t addr) {
    asm volatile("ldmatrix.sync.aligned.m8n8.x4.shared.b16 {%0,%1,%2,%3}, [%4];"
                 : "=r"(r[0]), "=r"(r[1]), "=r"(r[2]), "=r"(r[3]) : "r"(addr));
}
__device__ __forceinline__ void cp16(uint32_t dst, const void* src) {
    asm volatile("cp.async.cg.shared.global [%0], [%1], 16;"
                 :: "r"(dst), "l"(src) : "memory");
}

// ---------------- K1: per-token argmax + per-chunk histogram ----------------
// Staging rows padded to T+1=65 floats -> conflict-free reads.
__global__ void k_argmax_count(const float* __restrict__ sim) {
    int b = blockIdx.y, ch = blockIdx.x, tid = threadIdx.x;
    __shared__ float ss[CHUNK * (T + 1)];   // 33.3 KB
    __shared__ int   hist[T];

    const float4* src = (const float4*)(sim + ((size_t)(b * N + ch * CHUNK)) * T);
#pragma unroll
    for (int i = tid; i < CHUNK * T / 4; i += CHUNK) {
        float4 v = src[i];
        int row = i >> 4, c = (i & 15) * 4;
        float* d = ss + row * (T + 1) + c;
        d[0] = v.x; d[1] = v.y; d[2] = v.z; d[3] = v.w;
    }
    if (tid < T) hist[tid] = 0;
    __syncthreads();

    const float* row = ss + tid * (T + 1);
    float best = row[0];
    int   bi   = 0;
#pragma unroll
    for (int j = 1; j < T; j++) {
        float v = row[j];
        if (v > best) { best = v; bi = j; }   // first-max == jnp.argmax tie rule
    }
    g_tkid[b * N + ch * CHUNK + tid] = bi;
    atomicAdd(&hist[bi], 1);
    __syncthreads();
    if (tid < T) g_counts[(b * T + tid) * NCH + ch] = hist[tid];
}

// ---------------- K2: per-batch exclusive scan of counts + W fp16 convert ----
__global__ void k_scan(const float* __restrict__ W) {
    const int PER = (T * NCH) / 1024;   // 8
    int b = blockIdx.x, tid = threadIdx.x;
    __shared__ int t1[1024], t2[1024];
    int* cnt = g_counts + b * T * NCH;

    // fold in W->fp16 conversion (4 blocks x 1024 thr x 4 float4 = 16384)
#pragma unroll
    for (int j = 0; j < 4; j++) {
        int i = (b * 1024 + tid) * 4 + j;
        float4 v = ((const float4*)W)[i];
        __half2 a = __floats2half2_rn(v.x, v.y);
        __half2 c = __floats2half2_rn(v.z, v.w);
        uint2 o;
        o.x = *(uint32_t*)&a;
        o.y = *(uint32_t*)&c;
        *(uint2*)(g_wf + i * 4) = o;
    }

    int v[PER];
    int s = 0;
#pragma unroll
    for (int i = 0; i < PER; i++) { v[i] = cnt[tid * PER + i]; s += v[i]; }
    t1[tid] = s;
    __syncthreads();

    int* a  = t1;
    int* bb = t2;
    for (int off = 1; off < 1024; off <<= 1) {
        int x = a[tid];
        if (tid >= off) x += a[tid - off];
        bb[tid] = x;
        __syncthreads();
        int* tmp = a; a = bb; bb = tmp;
    }
    int pre = (tid == 0) ? 0 : a[tid - 1];
#pragma unroll
    for (int i = 0; i < PER; i++) { cnt[tid * PER + i] = pre; pre += v[i]; }
}

// ---------------- K3: stable scatter (match_any rank, no serial loop) --------
__global__ void k_scatter() {
    int b = blockIdx.y, ch = blockIdx.x, tid = threadIdx.x;
    __shared__ int wcnt[4][T];
    int w = tid >> 5, lane = tid & 31;
    for (int i = tid; i < 4 * T; i += CHUNK) ((int*)wcnt)[i] = 0;
    __syncthreads();

    int token = ch * CHUNK + tid;
    int key   = g_tkid[b * N + token];
    unsigned mask  = __match_any_sync(0xffffffffu, key);
    int lrank  = __popc(mask & ((1u << lane) - 1));
    int leader = __ffs(mask) - 1;
    if (lane == leader) wcnt[w][key] = __popc(mask);
    __syncthreads();

    int rank = lrank;
#pragma unroll
    for (int ww = 0; ww < 4; ww++)
        if (ww < w) rank += wcnt[ww][key];
    int pos = g_counts[(b * T + key) * NCH + ch] + rank;
    g_sortidx[b * N + pos] = token;
}

// ---------------- K4: grouped attention via warp MMA -------------------------
// QK: bf16 3-term split. PV: P fp16 hi/lo x V single fp16 (2 MMAs).
// Gather: 8 threads per token row (coalesced 128-B segments, 4 rows/warp)
// -> ~4x fewer L1 wavefronts than the old 2-threads-per-row mapping.
#define ATP 40
#define VTP 136
#define SQH 0
#define SQL (SQH + GS * ATP * 2)          // 10240 each
#define SKH (SQL + GS * ATP * 2)
#define SKL (SKH + GS * ATP * 2)
#define SVH (SKL + GS * ATP * 2)          // Vt fp16: 32*272 = 8704
#define STOK (SVH + D * VTP * 2)
#define SM_ATTN (STOK + GS * 4)           // 50,176 B

__global__ void __launch_bounds__(256, 2)
k_attn_mma(const float* __restrict__ qkv, const float* __restrict__ logit_scale) {
    extern __shared__ char sm[];
    uint32_t sb = smem_u32(sm);
    int head = blockIdx.x, g = blockIdx.y, b = blockIdx.z;
    int tid = threadIdx.x;
    int* toks = (int*)(sm + STOK);

    float scale = __expf(fminf(logit_scale[0], 4.6051701859880914f));  // log(100)

    // ---- gather: 8 threads per token row, 4 iterations of 32 rows ----
    {
        int s = tid & 7;                     // float4 index within 128-B section
        int rb = tid >> 3;                   // row 0..31 within iteration
        __half* vhp = (__half*)(sm + SVH);
#pragma unroll
        for (int it = 0; it < 4; it++) {
            int r = rb + it * 32;
            int token = g_sortidx[b * N + g * GS + r];
            if (s == 0) toks[r] = token;
            const float4* base =
                (const float4*)(qkv + ((size_t)(b * N) + token) * C3 + head * D);

            // q (pre-scaled, bf16 split)
            float4 vq = base[s];
            vq.x *= scale; vq.y *= scale; vq.z *= scale; vq.w *= scale;
            uint32_t h0, l0, h1, l1;
            split2(vq.x, vq.y, h0, l0);
            split2(vq.z, vq.w, h1, l1);
            *(uint2*)(sm + SQH + r * (ATP * 2) + s * 8) = make_uint2(h0, h1);
            *(uint2*)(sm + SQL + r * (ATP * 2) + s * 8) = make_uint2(l0, l1);

            // k (bf16 split)
            float4 vk = base[64 + s];
            split2(vk.x, vk.y, h0, l0);
            split2(vk.z, vk.w, h1, l1);
            *(uint2*)(sm + SKH + r * (ATP * 2) + s * 8) = make_uint2(h0, h1);
            *(uint2*)(sm + SKL + r * (ATP * 2) + s * 8) = make_uint2(l0, l1);

            // v (single fp16, transposed)
            float4 vv = base[128 + s];
            __half2 H0 = __floats2half2_rn(vv.x, vv.y);
            __half2 H1 = __floats2half2_rn(vv.z, vv.w);
            int d0 = s * 4;
            vhp[(d0 + 0) * VTP + r] = H0.x;
            vhp[(d0 + 1) * VTP + r] = H0.y;
            vhp[(d0 + 2) * VTP + r] = H1.x;
            vhp[(d0 + 3) * VTP + r] = H1.y;
        }
    }
    __syncthreads();

    int w = tid >> 5, lane = tid & 31;
    int gq = lane >> 2, t = lane & 3;
    int quad = lane >> 3, rrow = lane & 7;   // ldmatrix lane decomposition

    // ---- Q fragments via ldmatrix.x4 (A-operand, 16 rows x k16 per ki) ----
    uint32_t qh[2][4], ql[2][4];
    {
        int qrow = w * 16 + (quad & 1) * 8 + rrow;
#pragma unroll
        for (int ki = 0; ki < 2; ki++) {
            uint32_t off = qrow * 80 + ki * 32 + (quad >> 1) * 16;
            ldsm4(qh[ki], sb + SQH + off);
            ldsm4(ql[ki], sb + SQL + off);
        }
    }

    // ---- S = (scale*Q) K^T, 16x128 per warp in registers ----
    float S[16][4];
#pragma unroll
    for (int ni = 0; ni < 16; ni++)
#pragma unroll
        for (int rr = 0; rr < 4; rr++) S[ni][rr] = 0.f;

#pragma unroll
    for (int np = 0; np < 8; np++) {         // pairs of 8-key B tiles
        int krow = np * 16 + (quad >> 1) * 8 + rrow;
#pragma unroll
        for (int ki = 0; ki < 2; ki++) {
            uint32_t off = krow * 80 + ki * 32 + (quad & 1) * 16;
            uint32_t bh[4], bl[4];
            ldsm4(bh, sb + SKH + off);       // {b0,b1}=ni_even, {b2,b3}=ni_odd
            ldsm4(bl, sb + SKL + off);
            mma16816(S[2 * np],     qh[ki], bh);
            mma16816(S[2 * np],     qh[ki], bl);
            mma16816(S[2 * np],     ql[ki], bh);
            mma16816(S[2 * np + 1], qh[ki], bh + 2);
            mma16816(S[2 * np + 1], qh[ki], bl + 2);
            mma16816(S[2 * np + 1], ql[ki], bh + 2);
        }
    }

    // ---- softmax (two-pass, quad-shuffle row reductions) ----
    float mx0 = -INFINITY, mx1 = -INFINITY;
#pragma unroll
    for (int ni = 0; ni < 16; ni++) {
        mx0 = fmaxf(mx0, fmaxf(S[ni][0], S[ni][1]));
        mx1 = fmaxf(mx1, fmaxf(S[ni][2], S[ni][3]));
    }
#pragma unroll
    for (int x = 1; x <= 2; x <<= 1) {
        mx0 = fmaxf(mx0, __shfl_xor_sync(0xffffffffu, mx0, x));
        mx1 = fmaxf(mx1, __shfl_xor_sync(0xffffffffu, mx1, x));
    }

    float sm0 = 0.f, sm1 = 0.f;
#pragma unroll
    for (int ni = 0; ni < 16; ni++) {
        S[ni][0] = __expf(S[ni][0] - mx0);
        S[ni][1] = __expf(S[ni][1] - mx0);
        S[ni][2] = __expf(S[ni][2] - mx1);
        S[ni][3] = __expf(S[ni][3] - mx1);
        sm0 += S[ni][0] + S[ni][1];
        sm1 += S[ni][2] + S[ni][3];
    }
#pragma unroll
    for (int x = 1; x <= 2; x <<= 1) {
        sm0 += __shfl_xor_sync(0xffffffffu, sm0, x);
        sm1 += __shfl_xor_sync(0xffffffffu, sm1, x);
    }

    // ---- Y = P V  (P fp16 hi/lo from S registers, V single fp16) ----
    float Y[4][4];
#pragma unroll
    for (int nj = 0; nj < 4; nj++)
#pragma unroll
        for (int rr = 0; rr < 4; rr++) Y[nj][rr] = 0.f;

#pragma unroll
    for (int kk = 0; kk < 8; kk++) {
        uint32_t ph[4], pl[4];
        split2h(S[2 * kk][0],     S[2 * kk][1],     ph[0], pl[0]);
        split2h(S[2 * kk][2],     S[2 * kk][3],     ph[1], pl[1]);
        split2h(S[2 * kk + 1][0], S[2 * kk + 1][1], ph[2], pl[2]);
        split2h(S[2 * kk + 1][2], S[2 * kk + 1][3], ph[3], pl[3]);
#pragma unroll
        for (int njp = 0; njp < 2; njp++) {
            int vrow = njp * 16 + (quad >> 1) * 8 + rrow;
            uint32_t off = vrow * 272 + kk * 32 + (quad & 1) * 16;
            uint32_t bv[4];
            ldsm4(bv, sb + SVH + off);       // {b0,b1}=nj_even, {b2,b3}=nj_odd
            mma16816h(Y[2 * njp],     ph, bv);
            mma16816h(Y[2 * njp],     pl, bv);
            mma16816h(Y[2 * njp + 1], ph, bv + 2);
            mma16816h(Y[2 * njp + 1], pl, bv + 2);
        }
    }

    // ---- epilogue: normalize, fp16 hi/lo split, scatter to ORIGINAL order ----
    float i0 = 1.0f / sm0, i1 = 1.0f / sm1;
    int row0 = w * 16 + gq;
    size_t off0 = ((size_t)(b * N) + toks[row0]) * C + head * D;
    size_t off1 = ((size_t)(b * N) + toks[row0 + 8]) * C + head * D;
#pragma unroll
    for (int nj = 0; nj < 4; nj++) {
        uint32_t hh, ll;
        split2h(Y[nj][0] * i0, Y[nj][1] * i0, hh, ll);
        *(uint32_t*)(g_yh + off0 + nj * 8 + 2 * t) = hh;
        *(uint32_t*)(g_yl + off0 + nj * 8 + 2 * t) = ll;
        split2h(Y[nj][2] * i1, Y[nj][3] * i1, hh, ll);
        *(uint32_t*)(g_yh + off1 + nj * 8 + 2 * t) = hh;
        *(uint32_t*)(g_yl + off1 + nj * 8 + 2 * t) = ll;
    }
}

// ---------------- K5: projection GEMM (y fp16 hi/lo x W single fp16) ---------
// Block 128(M) x 64(N), 8 warps (4m x 2n), warp tile 32x32, 2 MMAs per tile.
// Double-buffered cp.async pipeline; ldmatrix fragment loads.
#define PM 128
#define PN 64
#define PKC 64
#define PSTR 72                 // fp16 elements per smem row (144 B)
#define SA_HI 0
#define SA_LO (PM * PSTR * 2)
#define SB_W  (SA_LO + PM * PSTR * 2)
#define SM_BUF (SB_W + PN * PSTR * 2)     // 46080 B per buffer
#define SM_PROJ (2 * SM_BUF)              // 92160 B

__global__ void __launch_bounds__(256)
k_proj_mma(const float* __restrict__ bias, float* __restrict__ out) {
    extern __shared__ char sm[];
    uint32_t sb = smem_u32(sm);
    int tid = threadIdx.x;
    int wid = tid >> 5, lane = tid & 31;
    int g = lane >> 2, t = lane & 3;
    int quad = lane >> 3, rrow = lane & 7;   // ldmatrix lane decomposition
    int wm = wid >> 1, wn = wid & 1;          // 4 x 2 warp grid
    int m0 = blockIdx.y * PM, n0 = blockIdx.x * PN;

    // async fill of one chunk into buffer at byte offset `boff`
    auto fill = [&](int ch, uint32_t boff) {
        uint32_t bA = sb + boff;
#pragma unroll
        for (int i = tid; i < PM * (PKC / 8); i += 256) {   // 1024 segs, 4 iters
            int r = i >> 3, s = i & 7;
            size_t src = (size_t)(m0 + r) * C + ch * PKC + s * 8;
            uint32_t off = (uint32_t)(r * (PSTR * 2) + s * 16);
            cp16(bA + SA_HI + off, g_yh + src);
            cp16(bA + SA_LO + off, g_yl + src);
        }
#pragma unroll
        for (int i = tid; i < PN * (PKC / 8); i += 256) {   // 512 segs, 2 iters
            int r = i >> 3, s = i & 7;
            size_t src = (size_t)(n0 + r) * C + ch * PKC + s * 8;
            uint32_t off = (uint32_t)(r * (PSTR * 2) + s * 16);
            cp16(bA + SB_W + off, g_wf + src);
        }
        asm volatile("cp.async.commit_group;" ::: "memory");
    };

    float acc[2][4][4];
#pragma unroll
    for (int mi = 0; mi < 2; mi++)
#pragma unroll
        for (int ni = 0; ni < 4; ni++)
#pragma unroll
            for (int r = 0; r < 4; r++) acc[mi][ni][r] = 0.f;

    fill(0, 0);
    int cur = 0;

#pragma unroll
    for (int ch = 0; ch < C / PKC; ch++) {
        if (ch < C / PKC - 1) {
            fill(ch + 1, (uint32_t)((cur ^ 1) * SM_BUF));
            asm volatile("cp.async.wait_group 1;" ::: "memory");
        } else {
            asm volatile("cp.async.wait_group 0;" ::: "memory");
        }
        __syncthreads();

        uint32_t bufb = sb + cur * SM_BUF;

#pragma unroll
        for (int ksi = 0; ksi < PKC / 16; ksi++) {
            uint32_t ah[2][4], al[2][4];
#pragma unroll
            for (int mi = 0; mi < 2; mi++) {
                int arow = wm * 32 + mi * 16 + (quad & 1) * 8 + rrow;
                uint32_t off = (uint32_t)(arow * 144 + ksi * 32 + (quad >> 1) * 16);
                ldsm4(ah[mi], bufb + SA_HI + off);
                ldsm4(al[mi], bufb + SA_LO + off);
            }
            uint32_t bfr[2][4];
#pragma unroll
            for (int njp = 0; njp < 2; njp++) {
                int brow = wn * 32 + njp * 16 + (quad >> 1) * 8 + rrow;
                uint32_t off = (uint32_t)(brow * 144 + ksi * 32 + (quad & 1) * 16);
                ldsm4(bfr[njp], bufb + SB_W + off);   // {0,1}=ni even, {2,3}=ni odd
            }
#pragma unroll
            for (int mi = 0; mi < 2; mi++)
#pragma unroll
                for (int ni = 0; ni < 4; ni++) {
                    const uint32_t* bp = bfr[ni >> 1] + (ni & 1) * 2;
                    mma16816h(acc[mi][ni], ah[mi], bp);   // hi term
                    mma16816h(acc[mi][ni], al[mi], bp);   // lo term
                }
        }
        __syncthreads();   // MMA reads done before this buffer is refilled
        cur ^= 1;
    }

#pragma unroll
    for (int ni = 0; ni < 4; ni++) {
        int cn = n0 + wn * 32 + ni * 8 + t * 2;
        float2 bb = *(const float2*)(bias + cn);
#pragma unroll
        for (int mi = 0; mi < 2; mi++) {
            int r0 = m0 + wm * 32 + mi * 16 + g;
            float2 o0, o1;
            o0.x = acc[mi][ni][0] + bb.x;
            o0.y = acc[mi][ni][1] + bb.y;
            o1.x = acc[mi][ni][2] + bb.x;
            o1.y = acc[mi][ni][3] + bb.y;
            *(float2*)(out + (size_t)r0 * C + cn)       = o0;
            *(float2*)(out + (size_t)(r0 + 8) * C + cn) = o1;
        }
    }
}

// ---------------- launch ----------------
extern "C" void kernel_launch(void* const* d_in, const int* in_sizes, int n_in,
                              void* d_out, int out_size) {
    const float* qkv  = (const float*)d_in[0];
    const float* sim  = (const float*)d_in[1];
    const float* W    = (const float*)d_in[2];
    const float* bias = (const float*)d_in[3];
    const float* ls   = (const float*)d_in[4];
    float* out = (float*)d_out;

    cudaFuncSetAttribute(k_attn_mma, cudaFuncAttributeMaxDynamicSharedMemorySize,
                         SM_ATTN);
    cudaFuncSetAttribute(k_proj_mma, cudaFuncAttributeMaxDynamicSharedMemorySize,
                         SM_PROJ);

    k_argmax_count<<<dim3(NCH, B), CHUNK>>>(sim);
    k_scan<<<B, 1024>>>(W);
    k_scatter<<<dim3(NCH, B), CHUNK>>>();
    k_attn_mma<<<dim3(HDS, NG, B), 256, SM_ATTN>>>(qkv, ls);
    k_proj_mma<<<dim3(C / PN, (B * N) / PM), 256, SM_PROJ>>>(bias, out);
}

// round 16
// speedup vs baseline: 1.6471x; 1.2336x over previous
#include <cuda_runtime.h>
#include <cuda_bf16.h>
#include <cuda_fp16.h>
#include <math.h>
#include <cstdint>

// Problem constants (fixed by the dataset)
#define B    4
#define N    16384
#define C    256
#define C3   768
#define T    64        // categories
#define HDS  8
#define D    32        // head dim
#define GS   128       // group size
#define NG   128       // groups per batch
#define CHUNK 128
#define NCH   128      // N / CHUNK

// ---------------- scratch (static device allocations only) ----------------
__device__ int   g_tkid[B * N];
__device__ int   g_counts[B * T * NCH];     // [b][key][chunk], scanned in place
__device__ int   g_sortidx[B * N];          // sorted position -> original token
// attention output in ORIGINAL token order, single fp16
__device__ __half g_yf[(size_t)B * N * C];
// projection weight, single fp16
__device__ __half g_wf[C * C];

// bf16 hi/lo split of a pair of floats, packed as bf16x2 words
__device__ __forceinline__ void split2(float a, float b, uint32_t& hi, uint32_t& lo) {
    __nv_bfloat162 h = __floats2bfloat162_rn(a, b);
    float ra = a - __bfloat162float(h.x);
    float rb = b - __bfloat162float(h.y);
    __nv_bfloat162 l = __floats2bfloat162_rn(ra, rb);
    hi = *(uint32_t*)&h;
    lo = *(uint32_t*)&l;
}
// fp16 hi/lo split (residual exact to ~2^-22)
__device__ __forceinline__ void split2h(float a, float b, uint32_t& hi, uint32_t& lo) {
    __half2 h = __floats2half2_rn(a, b);
    float ra = a - __low2float(h);
    float rb = b - __high2float(h);
    __half2 l = __floats2half2_rn(ra, rb);
    hi = *(uint32_t*)&h;
    lo = *(uint32_t*)&l;
}

// warp-level bf16 MMA, fp32 accumulate
__device__ __forceinline__ void mma16816(float* c, const uint32_t* a, const uint32_t* b) {
    asm volatile(
        "mma.sync.aligned.m16n8k16.row.col.f32.bf16.bf16.f32 "
        "{%0,%1,%2,%3}, {%4,%5,%6,%7}, {%8,%9}, {%0,%1,%2,%3};"
        : "+f"(c[0]), "+f"(c[1]), "+f"(c[2]), "+f"(c[3])
        : "r"(a[0]), "r"(a[1]), "r"(a[2]), "r"(a[3]), "r"(b[0]), "r"(b[1]));
}
// warp-level fp16 MMA, fp32 accumulate
__device__ __forceinline__ void mma16816h(float* c, const uint32_t* a, const uint32_t* b) {
    asm volatile(
        "mma.sync.aligned.m16n8k16.row.col.f32.f16.f16.f32 "
        "{%0,%1,%2,%3}, {%4,%5,%6,%7}, {%8,%9}, {%0,%1,%2,%3};"
        : "+f"(c[0]), "+f"(c[1]), "+f"(c[2]), "+f"(c[3])
        : "r"(a[0]), "r"(a[1]), "r"(a[2]), "r"(a[3]), "r"(b[0]), "r"(b[1]));
}

__device__ __forceinline__ uint32_t smem_u32(const void* p) {
    uint32_t a;
    asm("{ .reg .u64 t; cvta.to.shared.u64 t, %1; cvt.u32.u64 %0, t; }"
        : "=r"(a) : "l"(p));
    return a;
}
__device__ __forceinline__ void ldsm4(uint32_t* r, uint32_t addr) {
    asm volatile("ldmatrix.sync.aligned.m8n8.x4.shared.b16 {%0,%1,%2,%3}, [%4];"
                 : "=r"(r[0]), "=r"(r[1]), "=r"(r[2]), "=r"(r[3]) : "r"(addr));
}
__device__ __forceinline__ void cp16(uint32_t dst, const void* src) {
    asm volatile("cp.async.cg.shared.global [%0], [%1], 16;"
                 :: "r"(dst), "l"(src) : "memory");
}

// ---------------- K1: per-token argmax + per-chunk histogram ----------------
// Staging rows padded to T+1=65 floats -> conflict-free reads.
__global__ void k_argmax_count(const float* __restrict__ sim) {
    int b = blockIdx.y, ch = blockIdx.x, tid = threadIdx.x;
    __shared__ float ss[CHUNK * (T + 1)];   // 33.3 KB
    __shared__ int   hist[T];

    const float4* src = (const float4*)(sim + ((size_t)(b * N + ch * CHUNK)) * T);
#pragma unroll
    for (int i = tid; i < CHUNK * T / 4; i += CHUNK) {
        float4 v = src[i];
        int row = i >> 4, c = (i & 15) * 4;
        float* d = ss + row * (T + 1) + c;
        d[0] = v.x; d[1] = v.y; d[2] = v.z; d[3] = v.w;
    }
    if (tid < T) hist[tid] = 0;
    __syncthreads();

    const float* row = ss + tid * (T + 1);
    float best = row[0];
    int   bi   = 0;
#pragma unroll
    for (int j = 1; j < T; j++) {
        float v = row[j];
        if (v > best) { best = v; bi = j; }   // first-max == jnp.argmax tie rule
    }
    g_tkid[b * N + ch * CHUNK + tid] = bi;
    atomicAdd(&hist[bi], 1);
    __syncthreads();
    if (tid < T) g_counts[(b * T + tid) * NCH + ch] = hist[tid];
}

// ---------------- K2: per-batch exclusive scan of counts + W fp16 convert ----
__global__ void k_scan(const float* __restrict__ W) {
    const int PER = (T * NCH) / 1024;   // 8
    int b = blockIdx.x, tid = threadIdx.x;
    __shared__ int t1[1024], t2[1024];
    int* cnt = g_counts + b * T * NCH;

    // fold in W->fp16 conversion (4 blocks x 1024 thr x 4 float4 = 16384)
#pragma unroll
    for (int j = 0; j < 4; j++) {
        int i = (b * 1024 + tid) * 4 + j;
        float4 v = ((const float4*)W)[i];
        __half2 a = __floats2half2_rn(v.x, v.y);
        __half2 c = __floats2half2_rn(v.z, v.w);
        uint2 o;
        o.x = *(uint32_t*)&a;
        o.y = *(uint32_t*)&c;
        *(uint2*)(g_wf + i * 4) = o;
    }

    int v[PER];
    int s = 0;
#pragma unroll
    for (int i = 0; i < PER; i++) { v[i] = cnt[tid * PER + i]; s += v[i]; }
    t1[tid] = s;
    __syncthreads();

    int* a  = t1;
    int* bb = t2;
    for (int off = 1; off < 1024; off <<= 1) {
        int x = a[tid];
        if (tid >= off) x += a[tid - off];
        bb[tid] = x;
        __syncthreads();
        int* tmp = a; a = bb; bb = tmp;
    }
    int pre = (tid == 0) ? 0 : a[tid - 1];
#pragma unroll
    for (int i = 0; i < PER; i++) { cnt[tid * PER + i] = pre; pre += v[i]; }
}

// ---------------- K3: stable scatter (match_any rank, no serial loop) --------
__global__ void k_scatter() {
    int b = blockIdx.y, ch = blockIdx.x, tid = threadIdx.x;
    __shared__ int wcnt[4][T];
    int w = tid >> 5, lane = tid & 31;
    for (int i = tid; i < 4 * T; i += CHUNK) ((int*)wcnt)[i] = 0;
    __syncthreads();

    int token = ch * CHUNK + tid;
    int key   = g_tkid[b * N + token];
    unsigned mask  = __match_any_sync(0xffffffffu, key);
    int lrank  = __popc(mask & ((1u << lane) - 1));
    int leader = __ffs(mask) - 1;
    if (lane == leader) wcnt[w][key] = __popc(mask);
    __syncthreads();

    int rank = lrank;
#pragma unroll
    for (int ww = 0; ww < 4; ww++)
        if (ww < w) rank += wcnt[ww][key];
    int pos = g_counts[(b * T + key) * NCH + ch] + rank;
    g_sortidx[b * N + pos] = token;
}

// ---------------- K4: grouped attention via warp MMA -------------------------
// QK: bf16 3-term split. PV: P fp16 hi/lo x V single fp16 (2 MMAs).
// Gather: 8 threads per token row (coalesced 128-B segments).
#define ATP 40
#define VTP 136
#define SQH 0
#define SQL (SQH + GS * ATP * 2)          // 10240 each
#define SKH (SQL + GS * ATP * 2)
#define SKL (SKH + GS * ATP * 2)
#define SVH (SKL + GS * ATP * 2)          // Vt fp16: 32*272 = 8704
#define STOK (SVH + D * VTP * 2)
#define SM_ATTN (STOK + GS * 4)           // 50,176 B

__global__ void __launch_bounds__(256, 2)
k_attn_mma(const float* __restrict__ qkv, const float* __restrict__ logit_scale) {
    extern __shared__ char sm[];
    uint32_t sb = smem_u32(sm);
    int head = blockIdx.x, g = blockIdx.y, b = blockIdx.z;
    int tid = threadIdx.x;
    int* toks = (int*)(sm + STOK);

    float scale = __expf(fminf(logit_scale[0], 4.6051701859880914f));  // log(100)

    // ---- gather: 8 threads per token row, 4 iterations of 32 rows ----
    {
        int s = tid & 7;                     // float4 index within 128-B section
        int rb = tid >> 3;                   // row 0..31 within iteration
        __half* vhp = (__half*)(sm + SVH);
#pragma unroll
        for (int it = 0; it < 4; it++) {
            int r = rb + it * 32;
            int token = g_sortidx[b * N + g * GS + r];
            if (s == 0) toks[r] = token;
            const float4* base =
                (const float4*)(qkv + ((size_t)(b * N) + token) * C3 + head * D);

            // q (pre-scaled, bf16 split)
            float4 vq = base[s];
            vq.x *= scale; vq.y *= scale; vq.z *= scale; vq.w *= scale;
            uint32_t h0, l0, h1, l1;
            split2(vq.x, vq.y, h0, l0);
            split2(vq.z, vq.w, h1, l1);
            *(uint2*)(sm + SQH + r * (ATP * 2) + s * 8) = make_uint2(h0, h1);
            *(uint2*)(sm + SQL + r * (ATP * 2) + s * 8) = make_uint2(l0, l1);

            // k (bf16 split)
            float4 vk = base[64 + s];
            split2(vk.x, vk.y, h0, l0);
            split2(vk.z, vk.w, h1, l1);
            *(uint2*)(sm + SKH + r * (ATP * 2) + s * 8) = make_uint2(h0, h1);
            *(uint2*)(sm + SKL + r * (ATP * 2) + s * 8) = make_uint2(l0, l1);

            // v (single fp16, transposed)
            float4 vv = base[128 + s];
            __half2 H0 = __floats2half2_rn(vv.x, vv.y);
            __half2 H1 = __floats2half2_rn(vv.z, vv.w);
            int d0 = s * 4;
            vhp[(d0 + 0) * VTP + r] = H0.x;
            vhp[(d0 + 1) * VTP + r] = H0.y;
            vhp[(d0 + 2) * VTP + r] = H1.x;
            vhp[(d0 + 3) * VTP + r] = H1.y;
        }
    }
    __syncthreads();

    int w = tid >> 5, lane = tid & 31;
    int gq = lane >> 2, t = lane & 3;
    int quad = lane >> 3, rrow = lane & 7;   // ldmatrix lane decomposition

    // ---- Q fragments via ldmatrix.x4 (A-operand, 16 rows x k16 per ki) ----
    uint32_t qh[2][4], ql[2][4];
    {
        int qrow = w * 16 + (quad & 1) * 8 + rrow;
#pragma unroll
        for (int ki = 0; ki < 2; ki++) {
            uint32_t off = qrow * 80 + ki * 32 + (quad >> 1) * 16;
            ldsm4(qh[ki], sb + SQH + off);
            ldsm4(ql[ki], sb + SQL + off);
        }
    }

    // ---- S = (scale*Q) K^T, 16x128 per warp in registers ----
    float S[16][4];
#pragma unroll
    for (int ni = 0; ni < 16; ni++)
#pragma unroll
        for (int rr = 0; rr < 4; rr++) S[ni][rr] = 0.f;

#pragma unroll
    for (int np = 0; np < 8; np++) {         // pairs of 8-key B tiles
        int krow = np * 16 + (quad >> 1) * 8 + rrow;
#pragma unroll
        for (int ki = 0; ki < 2; ki++) {
            uint32_t off = krow * 80 + ki * 32 + (quad & 1) * 16;
            uint32_t bh[4], bl[4];
            ldsm4(bh, sb + SKH + off);       // {b0,b1}=ni_even, {b2,b3}=ni_odd
            ldsm4(bl, sb + SKL + off);
            mma16816(S[2 * np],     qh[ki], bh);
            mma16816(S[2 * np],     qh[ki], bl);
            mma16816(S[2 * np],     ql[ki], bh);
            mma16816(S[2 * np + 1], qh[ki], bh + 2);
            mma16816(S[2 * np + 1], qh[ki], bl + 2);
            mma16816(S[2 * np + 1], ql[ki], bh + 2);
        }
    }

    // ---- softmax (two-pass, quad-shuffle row reductions) ----
    float mx0 = -INFINITY, mx1 = -INFINITY;
#pragma unroll
    for (int ni = 0; ni < 16; ni++) {
        mx0 = fmaxf(mx0, fmaxf(S[ni][0], S[ni][1]));
        mx1 = fmaxf(mx1, fmaxf(S[ni][2], S[ni][3]));
    }
#pragma unroll
    for (int x = 1; x <= 2; x <<= 1) {
        mx0 = fmaxf(mx0, __shfl_xor_sync(0xffffffffu, mx0, x));
        mx1 = fmaxf(mx1, __shfl_xor_sync(0xffffffffu, mx1, x));
    }

    float sm0 = 0.f, sm1 = 0.f;
#pragma unroll
    for (int ni = 0; ni < 16; ni++) {
        S[ni][0] = __expf(S[ni][0] - mx0);
        S[ni][1] = __expf(S[ni][1] - mx0);
        S[ni][2] = __expf(S[ni][2] - mx1);
        S[ni][3] = __expf(S[ni][3] - mx1);
        sm0 += S[ni][0] + S[ni][1];
        sm1 += S[ni][2] + S[ni][3];
    }
#pragma unroll
    for (int x = 1; x <= 2; x <<= 1) {
        sm0 += __shfl_xor_sync(0xffffffffu, sm0, x);
        sm1 += __shfl_xor_sync(0xffffffffu, sm1, x);
    }

    // ---- Y = P V  (P fp16 hi/lo from S registers, V single fp16) ----
    float Y[4][4];
#pragma unroll
    for (int nj = 0; nj < 4; nj++)
#pragma unroll
        for (int rr = 0; rr < 4; rr++) Y[nj][rr] = 0.f;

#pragma unroll
    for (int kk = 0; kk < 8; kk++) {
        uint32_t ph[4], pl[4];
        split2h(S[2 * kk][0],     S[2 * kk][1],     ph[0], pl[0]);
        split2h(S[2 * kk][2],     S[2 * kk][3],     ph[1], pl[1]);
        split2h(S[2 * kk + 1][0], S[2 * kk + 1][1], ph[2], pl[2]);
        split2h(S[2 * kk + 1][2], S[2 * kk + 1][3], ph[3], pl[3]);
#pragma unroll
        for (int njp = 0; njp < 2; njp++) {
            int vrow = njp * 16 + (quad >> 1) * 8 + rrow;
            uint32_t off = vrow * 272 + kk * 32 + (quad & 1) * 16;
            uint32_t bv[4];
            ldsm4(bv, sb + SVH + off);       // {b0,b1}=nj_even, {b2,b3}=nj_odd
            mma16816h(Y[2 * njp],     ph, bv);
            mma16816h(Y[2 * njp],     pl, bv);
            mma16816h(Y[2 * njp + 1], ph, bv + 2);
            mma16816h(Y[2 * njp + 1], pl, bv + 2);
        }
    }

    // ---- epilogue: normalize, single fp16, scatter to ORIGINAL order ----
    float i0 = 1.0f / sm0, i1 = 1.0f / sm1;
    int row0 = w * 16 + gq;
    size_t off0 = ((size_t)(b * N) + toks[row0]) * C + head * D;
    size_t off1 = ((size_t)(b * N) + toks[row0 + 8]) * C + head * D;
#pragma unroll
    for (int nj = 0; nj < 4; nj++) {
        __half2 h0 = __floats2half2_rn(Y[nj][0] * i0, Y[nj][1] * i0);
        __half2 h1 = __floats2half2_rn(Y[nj][2] * i1, Y[nj][3] * i1);
        *(uint32_t*)(g_yf + off0 + nj * 8 + 2 * t) = *(uint32_t*)&h0;
        *(uint32_t*)(g_yf + off1 + nj * 8 + 2 * t) = *(uint32_t*)&h1;
    }
}

// ---------------- K5: projection GEMM (y fp16 x W fp16, single term) ---------
// Block 128(M) x 64(N), 8 warps (4m x 2n), warp tile 32x32, 1 MMA per tile.
// Double-buffered cp.async pipeline; ldmatrix fragment loads.
#define PM 128
#define PN 64
#define PKC 64
#define PSTR 72                 // fp16 elements per smem row (144 B)
#define SA_Y  0
#define SB_W  (SA_Y + PM * PSTR * 2)
#define SM_BUF (SB_W + PN * PSTR * 2)     // 27648 B per buffer
#define SM_PROJ (2 * SM_BUF)              // 55296 B

__global__ void __launch_bounds__(256)
k_proj_mma(const float* __restrict__ bias, float* __restrict__ out) {
    extern __shared__ char sm[];
    uint32_t sb = smem_u32(sm);
    int tid = threadIdx.x;
    int wid = tid >> 5, lane = tid & 31;
    int g = lane >> 2, t = lane & 3;
    int quad = lane >> 3, rrow = lane & 7;   // ldmatrix lane decomposition
    int wm = wid >> 1, wn = wid & 1;          // 4 x 2 warp grid
    int m0 = blockIdx.y * PM, n0 = blockIdx.x * PN;

    // async fill of one chunk into buffer at byte offset `boff`
    auto fill = [&](int ch, uint32_t boff) {
        uint32_t bA = sb + boff;
#pragma unroll
        for (int i = tid; i < PM * (PKC / 8); i += 256) {   // 1024 segs, 4 iters
            int r = i >> 3, s = i & 7;
            size_t src = (size_t)(m0 + r) * C + ch * PKC + s * 8;
            uint32_t off = (uint32_t)(r * (PSTR * 2) + s * 16);
            cp16(bA + SA_Y + off, g_yf + src);
        }
#pragma unroll
        for (int i = tid; i < PN * (PKC / 8); i += 256) {   // 512 segs, 2 iters
            int r = i >> 3, s = i & 7;
            size_t src = (size_t)(n0 + r) * C + ch * PKC + s * 8;
            uint32_t off = (uint32_t)(r * (PSTR * 2) + s * 16);
            cp16(bA + SB_W + off, g_wf + src);
        }
        asm volatile("cp.async.commit_group;" ::: "memory");
    };

    float acc[2][4][4];
#pragma unroll
    for (int mi = 0; mi < 2; mi++)
#pragma unroll
        for (int ni = 0; ni < 4; ni++)
#pragma unroll
            for (int r = 0; r < 4; r++) acc[mi][ni][r] = 0.f;

    fill(0, 0);
    int cur = 0;

#pragma unroll
    for (int ch = 0; ch < C / PKC; ch++) {
        if (ch < C / PKC - 1) {
            fill(ch + 1, (uint32_t)((cur ^ 1) * SM_BUF));
            asm volatile("cp.async.wait_group 1;" ::: "memory");
        } else {
            asm volatile("cp.async.wait_group 0;" ::: "memory");
        }
        __syncthreads();

        uint32_t bufb = sb + cur * SM_BUF;

#pragma unroll
        for (int ksi = 0; ksi < PKC / 16; ksi++) {
            uint32_t ah[2][4];
#pragma unroll
            for (int mi = 0; mi < 2; mi++) {
                int arow = wm * 32 + mi * 16 + (quad & 1) * 8 + rrow;
                uint32_t off = (uint32_t)(arow * 144 + ksi * 32 + (quad >> 1) * 16);
                ldsm4(ah[mi], bufb + SA_Y + off);
            }
            uint32_t bfr[2][4];
#pragma unroll
            for (int njp = 0; njp < 2; njp++) {
                int brow = wn * 32 + njp * 16 + (quad >> 1) * 8 + rrow;
                uint32_t off = (uint32_t)(brow * 144 + ksi * 32 + (quad & 1) * 16);
                ldsm4(bfr[njp], bufb + SB_W + off);   // {0,1}=ni even, {2,3}=ni odd
            }
#pragma unroll
            for (int mi = 0; mi < 2; mi++)
#pragma unroll
                for (int ni = 0; ni < 4; ni++) {
                    const uint32_t* bp = bfr[ni >> 1] + (ni & 1) * 2;
                    mma16816h(acc[mi][ni], ah[mi], bp);
                }
        }
        __syncthreads();   // MMA reads done before this buffer is refilled
        cur ^= 1;
    }

#pragma unroll
    for (int ni = 0; ni < 4; ni++) {
        int cn = n0 + wn * 32 + ni * 8 + t * 2;
        float2 bb = *(const float2*)(bias + cn);
#pragma unroll
        for (int mi = 0; mi < 2; mi++) {
            int r0 = m0 + wm * 32 + mi * 16 + g;
            float2 o0, o1;
            o0.x = acc[mi][ni][0] + bb.x;
            o0.y = acc[mi][ni][1] + bb.y;
            o1.x = acc[mi][ni][2] + bb.x;
            o1.y = acc[mi][ni][3] + bb.y;
            *(float2*)(out + (size_t)r0 * C + cn)       = o0;
            *(float2*)(out + (size_t)(r0 + 8) * C + cn) = o1;
        }
    }
}

// ---------------- launch ----------------
extern "C" void kernel_launch(void* const* d_in, const int* in_sizes, int n_in,
                              void* d_out, int out_size) {
    const float* qkv  = (const float*)d_in[0];
    const float* sim  = (const float*)d_in[1];
    const float* W    = (const float*)d_in[2];
    const float* bias = (const float*)d_in[3];
    const float* ls   = (const float*)d_in[4];
    float* out = (float*)d_out;

    cudaFuncSetAttribute(k_attn_mma, cudaFuncAttributeMaxDynamicSharedMemorySize,
                         SM_ATTN);
    cudaFuncSetAttribute(k_proj_mma, cudaFuncAttributeMaxDynamicSharedMemorySize,
                         SM_PROJ);

    k_argmax_count<<<dim3(NCH, B), CHUNK>>>(sim);
    k_scan<<<B, 1024>>>(W);
    k_scatter<<<dim3(NCH, B), CHUNK>>>();
    k_attn_mma<<<dim3(HDS, NG, B), 256, SM_ATTN>>>(qkv, ls);
    k_proj_mma<<<dim3(C / PN, (B * N) / PM), 256, SM_PROJ>>>(bias, out);
}